// round 9
// baseline (speedup 1.0000x reference)
#include <cuda_runtime.h>
#include <cuda_bf16.h>
#include <cstdint>

// ---------------------------------------------------------------------------
// DIN forward.
//  Kernel F: fold per-b attention weights -> g_w12t[b][j][k], g_qc[b][j]
//  Kernel A: scores via mma.sync tf32 (3xTF32), B-splits precomputed,
//            H1 aliases KEYS -> 87.5KB smem -> 2 CTAs/SM
//  Kernel B: softmax + interest
//  Kernel C: final MLP (fp32, k-split)
// ---------------------------------------------------------------------------

#define B_ROWS 4096
#define T_LEN  200
#define TPAD   224
#define E_DIM  64

__device__ float g_w12t[B_ROWS * 64 * 64];   // [b][j][k]
__device__ float g_qc[B_ROWS * 64];
__device__ float g_scores[B_ROWS * TPAD];
__device__ float g_interest[B_ROWS * E_DIM];

__device__ __forceinline__ float2 fma2(float2 a, float2 b, float2 c) {
    float2 d;
    asm("fma.rn.f32x2 %0, %1, %2, %3;"
        : "=l"(*(unsigned long long*)&d)
        : "l"(*(unsigned long long*)&a),
          "l"(*(unsigned long long*)&b),
          "l"(*(unsigned long long*)&c));
    return d;
}

__device__ __forceinline__ uint32_t f2tf32(float f) {
    uint32_t u;
    asm("cvt.rna.tf32.f32 %0, %1;" : "=r"(u) : "f"(f));
    return u;
}
__device__ __forceinline__ void split3(float x, uint32_t& hi, uint32_t& lo) {
    hi = f2tf32(x);
    lo = f2tf32(x - __uint_as_float(hi));
}
// D += A*B  (m16n8k8, A row-major, B col-major, tf32 in, f32 acc)
__device__ __forceinline__ void mma168(float* d, const uint32_t* a, const uint32_t* b) {
    asm volatile(
        "mma.sync.aligned.m16n8k8.row.col.f32.tf32.tf32.f32 "
        "{%0,%1,%2,%3}, {%4,%5,%6,%7}, {%8,%9}, {%0,%1,%2,%3};"
        : "+f"(d[0]), "+f"(d[1]), "+f"(d[2]), "+f"(d[3])
        : "r"(a[0]), "r"(a[1]), "r"(a[2]), "r"(a[3]), "r"(b[0]), "r"(b[1]));
}

// ---------------------------------------------------------------------------
// Kernel F: fold weights per b, store transposed [j][k].
// ---------------------------------------------------------------------------
__global__ void __launch_bounds__(256, 4)
din_fold_kernel(const int* __restrict__ tgt,
                const float* __restrict__ item_table,
                const float* __restrict__ w1, const float* __restrict__ b1)
{
    __shared__ float Q[64];
    __shared__ float SM[64 * 65];
    const int b   = blockIdx.x;
    const int tid = threadIdx.x;

    if (tid < 64) Q[tid] = item_table[(long)tgt[b] * 64 + tid];
    __syncthreads();

    for (int i = tid; i < 4096; i += 256) {
        int k = i >> 6, j = i & 63;
        SM[k * 65 + j] = w1[i] + w1[8192 + i] + Q[k] * w1[12288 + i];
    }
    __syncthreads();
    for (int i = tid; i < 4096; i += 256) {
        int j = i >> 6, k = i & 63;
        g_w12t[(long)b * 4096 + i] = SM[k * 65 + j];
    }
    if (tid < 64) {
        float s = b1[tid];
        #pragma unroll 8
        for (int e = 0; e < 64; ++e)
            s += Q[e] * (w1[4096 + e * 64 + tid] - w1[8192 + e * 64 + tid]);
        g_qc[b * 64 + tid] = s;
    }
}

// ---------------------------------------------------------------------------
// Kernel A: scores via mma.sync tf32. grid = 2*B (two 128-t tiles per b),
// 256 thr (8 warps x m16). B hi/lo precomputed; H1 aliases KEYS.
// smem (fp32 words, padded stride 68):
//   KEYS/H1[128][68] | W12H[64][68] | W12L[64][68] | W2H[32][68] | W2L[32][68]
//   | QC[64] | B2[32] | WO[32]   -> 21888 floats = 87.5 KB -> 2 CTAs/SM
// ---------------------------------------------------------------------------
#define SA_KEYS  0
#define SA_W12H  8704
#define SA_W12L  13056
#define SA_W2H   17408
#define SA_W2L   19584
#define SA_QC    21760
#define SA_B2    21824
#define SA_WO    21856
#define SMEMA_FLOATS 21888
#define SMEMA_BYTES  (SMEMA_FLOATS * 4)

__global__ void __launch_bounds__(256, 2)
din_scores_kernel(const int* __restrict__ tgt,
                  const int* __restrict__ hist,
                  const int* __restrict__ mask,
                  const float* __restrict__ item_table,
                  const float* __restrict__ w2, const float* __restrict__ b2,
                  const float* __restrict__ wo, const float* __restrict__ bo)
{
    extern __shared__ float sm[];
    float* KEYS = sm + SA_KEYS;      // aliased by H1 after A-frag preload
    float* H1   = sm + SA_KEYS;
    float* W12H = sm + SA_W12H;
    float* W12L = sm + SA_W12L;
    float* W2H  = sm + SA_W2H;
    float* W2L  = sm + SA_W2L;
    float* QC   = sm + SA_QC;
    float* B2S  = sm + SA_B2;
    float* WOS  = sm + SA_WO;

    const int b    = blockIdx.x >> 1;
    const int t0   = (blockIdx.x & 1) * 128;
    const int tid  = threadIdx.x;
    const int lane = tid & 31;
    const int wid  = tid >> 5;      // 0..7
    const int gid  = lane >> 2;     // 0..7
    const int tig  = lane & 3;      // 0..3

    // ---- stage operands ----
    for (int i = tid; i < 128 * 16; i += 256) {
        int f4 = i & 15;
        int m  = i >> 4;
        int tg = t0 + m;
        float4 v = make_float4(0.f, 0.f, 0.f, 0.f);
        if (tg < T_LEN) {
            int row = hist[b * T_LEN + tg];
            v = *(const float4*)(item_table + (long)row * E_DIM + 4 * f4);
        }
        *(float4*)(KEYS + m * 68 + 4 * f4) = v;
    }
    for (int i = tid; i < 4096; i += 256) {
        int j = i >> 6, k = i & 63;
        uint32_t hi, lo;
        split3(g_w12t[(long)b * 4096 + i], hi, lo);
        W12H[j * 68 + k] = __uint_as_float(hi);
        W12L[j * 68 + k] = __uint_as_float(lo);
    }
    for (int i = tid; i < 2048; i += 256) {
        int n = i & 31, j = i >> 5;
        uint32_t hi, lo;
        split3(w2[i], hi, lo);
        W2H[n * 68 + j] = __uint_as_float(hi);
        W2L[n * 68 + j] = __uint_as_float(lo);
    }
    if (tid < 64) QC[tid] = g_qc[b * 64 + tid];
    if (tid < 32) { B2S[tid] = b2[tid]; WOS[tid] = wo[tid]; }
    __syncthreads();

    const int mb = wid * 16;

    // ---- GEMM1: H1[m][j] = relu(KEYS @ W12T^T + qc) ----
    {
        // hoist A fragments into registers (KEYS is dead afterwards)
        uint32_t ahi[8][4], alo[8][4];
        #pragma unroll
        for (int ks = 0; ks < 8; ++ks) {
            float r0 = KEYS[(mb + gid)     * 68 + ks * 8 + tig];
            float r1 = KEYS[(mb + gid + 8) * 68 + ks * 8 + tig];
            float r2 = KEYS[(mb + gid)     * 68 + ks * 8 + tig + 4];
            float r3 = KEYS[(mb + gid + 8) * 68 + ks * 8 + tig + 4];
            split3(r0, ahi[ks][0], alo[ks][0]);
            split3(r1, ahi[ks][1], alo[ks][1]);
            split3(r2, ahi[ks][2], alo[ks][2]);
            split3(r3, ahi[ks][3], alo[ks][3]);
        }
        __syncthreads();   // all warps done reading KEYS; safe to overwrite as H1

        #pragma unroll
        for (int nt = 0; nt < 8; ++nt) {
            float acc[4] = {0.f, 0.f, 0.f, 0.f};
            #pragma unroll
            for (int ks = 0; ks < 8; ++ks) {
                const int roff = (nt * 8 + gid) * 68 + ks * 8 + tig;
                uint32_t bh[2], bl[2];
                bh[0] = __float_as_uint(W12H[roff]);
                bh[1] = __float_as_uint(W12H[roff + 4]);
                bl[0] = __float_as_uint(W12L[roff]);
                bl[1] = __float_as_uint(W12L[roff + 4]);
                mma168(acc, ahi[ks], bh);
                mma168(acc, ahi[ks], bl);
                mma168(acc, alo[ks], bh);
            }
            int j0 = nt * 8 + 2 * tig;
            float q0 = QC[j0], q1 = QC[j0 + 1];
            float2 r0 = make_float2(fmaxf(acc[0] + q0, 0.f), fmaxf(acc[1] + q1, 0.f));
            float2 r1 = make_float2(fmaxf(acc[2] + q0, 0.f), fmaxf(acc[3] + q1, 0.f));
            *(float2*)(H1 + (mb + gid)     * 68 + j0) = r0;
            *(float2*)(H1 + (mb + gid + 8) * 68 + j0) = r1;
        }
    }
    __syncthreads();

    // ---- GEMM2: scores = reduce_n relu(H1 @ W2T^T + b2)*wo ----
    {
        uint32_t ahi[8][4], alo[8][4];
        #pragma unroll
        for (int ks = 0; ks < 8; ++ks) {
            float r0 = H1[(mb + gid)     * 68 + ks * 8 + tig];
            float r1 = H1[(mb + gid + 8) * 68 + ks * 8 + tig];
            float r2 = H1[(mb + gid)     * 68 + ks * 8 + tig + 4];
            float r3 = H1[(mb + gid + 8) * 68 + ks * 8 + tig + 4];
            split3(r0, ahi[ks][0], alo[ks][0]);
            split3(r1, ahi[ks][1], alo[ks][1]);
            split3(r2, ahi[ks][2], alo[ks][2]);
            split3(r3, ahi[ks][3], alo[ks][3]);
        }
        float srow0 = 0.f, srow8 = 0.f;
        #pragma unroll
        for (int nt = 0; nt < 4; ++nt) {
            float acc[4] = {0.f, 0.f, 0.f, 0.f};
            #pragma unroll
            for (int ks = 0; ks < 8; ++ks) {
                const int roff = (nt * 8 + gid) * 68 + ks * 8 + tig;
                uint32_t bh[2], bl[2];
                bh[0] = __float_as_uint(W2H[roff]);
                bh[1] = __float_as_uint(W2H[roff + 4]);
                bl[0] = __float_as_uint(W2L[roff]);
                bl[1] = __float_as_uint(W2L[roff + 4]);
                mma168(acc, ahi[ks], bh);
                mma168(acc, ahi[ks], bl);
                mma168(acc, alo[ks], bh);
            }
            int n0 = nt * 8 + 2 * tig;
            float bb0 = B2S[n0], bb1 = B2S[n0 + 1];
            float w0 = WOS[n0],  w1v = WOS[n0 + 1];
            srow0 += fmaxf(acc[0] + bb0, 0.f) * w0 + fmaxf(acc[1] + bb1, 0.f) * w1v;
            srow8 += fmaxf(acc[2] + bb0, 0.f) * w0 + fmaxf(acc[3] + bb1, 0.f) * w1v;
        }
        srow0 += __shfl_xor_sync(0xffffffffu, srow0, 1);
        srow0 += __shfl_xor_sync(0xffffffffu, srow0, 2);
        srow8 += __shfl_xor_sync(0xffffffffu, srow8, 1);
        srow8 += __shfl_xor_sync(0xffffffffu, srow8, 2);

        if (tig == 0) {
            float bos = bo[0];
            int tg0 = t0 + mb + gid;
            int tg8 = tg0 + 8;
            if (tg0 < T_LEN)
                g_scores[b * TPAD + tg0] = mask[b * T_LEN + tg0] ? srow0 + bos : -1e9f;
            else if (tg0 < TPAD)
                g_scores[b * TPAD + tg0] = -1e9f;
            if (tg8 < T_LEN)
                g_scores[b * TPAD + tg8] = mask[b * T_LEN + tg8] ? srow8 + bos : -1e9f;
            else if (tg8 < TPAD)
                g_scores[b * TPAD + tg8] = -1e9f;
        }
    }
}

// ---------------------------------------------------------------------------
// Kernel B: softmax over 224 scores + interest vector (re-gather keys).
// ---------------------------------------------------------------------------
__global__ void __launch_bounds__(256, 8)
din_softmax_kernel(const int* __restrict__ hist,
                   const float* __restrict__ item_table)
{
    __shared__ float SC[TPAD];
    __shared__ float WG[TPAD];
    __shared__ float RED[8];
    __shared__ float SV[2];

    const int b    = blockIdx.x;
    const int tid  = threadIdx.x;
    const int lane = tid & 31;
    const int warp = tid >> 5;

    float s = (tid < TPAD) ? g_scores[b * TPAD + tid] : -3.4e38f;
    if (tid < TPAD) SC[tid] = s;

    float m = s;
    #pragma unroll
    for (int off = 16; off > 0; off >>= 1)
        m = fmaxf(m, __shfl_xor_sync(0xffffffffu, m, off));
    if (lane == 0) RED[warp] = m;
    __syncthreads();
    if (warp == 0) {
        float mm = (lane < 7) ? RED[lane] : -3.4e38f;
        #pragma unroll
        for (int off = 4; off > 0; off >>= 1)
            mm = fmaxf(mm, __shfl_xor_sync(0xffffffffu, mm, off));
        if (lane == 0) SV[0] = mm;
    }
    __syncthreads();

    float e = 0.f;
    if (tid < TPAD) {
        e = expf(SC[tid] - SV[0]);
        WG[tid] = e;
    }
    #pragma unroll
    for (int off = 16; off > 0; off >>= 1)
        e += __shfl_xor_sync(0xffffffffu, e, off);
    if (lane == 0) RED[warp] = e;
    __syncthreads();
    if (warp == 0) {
        float t2 = (lane < 7) ? RED[lane] : 0.f;
        #pragma unroll
        for (int off = 4; off > 0; off >>= 1)
            t2 += __shfl_xor_sync(0xffffffffu, t2, off);
        if (lane == 0) SV[1] = t2;
    }
    __syncthreads();

    const int e0 = warp * 8;
    float a0=0.f,a1=0.f,a2=0.f,a3=0.f,a4=0.f,a5=0.f,a6=0.f,a7=0.f;
    #pragma unroll
    for (int i = 0; i < 7; ++i) {
        int t = lane + 32 * i;
        float wv = WG[t];
        if (t < T_LEN) {
            int row = hist[b * T_LEN + t];
            const float* kp = item_table + (long)row * E_DIM + e0;
            float4 va = *(const float4*)(kp);
            float4 vb = *(const float4*)(kp + 4);
            a0 += wv * va.x; a1 += wv * va.y; a2 += wv * va.z; a3 += wv * va.w;
            a4 += wv * vb.x; a5 += wv * vb.y; a6 += wv * vb.z; a7 += wv * vb.w;
        }
    }
    #pragma unroll
    for (int off = 16; off > 0; off >>= 1) {
        a0 += __shfl_xor_sync(0xffffffffu, a0, off);
        a1 += __shfl_xor_sync(0xffffffffu, a1, off);
        a2 += __shfl_xor_sync(0xffffffffu, a2, off);
        a3 += __shfl_xor_sync(0xffffffffu, a3, off);
        a4 += __shfl_xor_sync(0xffffffffu, a4, off);
        a5 += __shfl_xor_sync(0xffffffffu, a5, off);
        a6 += __shfl_xor_sync(0xffffffffu, a6, off);
        a7 += __shfl_xor_sync(0xffffffffu, a7, off);
    }
    if (lane == 0) {
        float invs = 1.0f / SV[1];
        float* gi = g_interest + (long)b * E_DIM + e0;
        gi[0]=a0*invs; gi[1]=a1*invs; gi[2]=a2*invs; gi[3]=a3*invs;
        gi[4]=a4*invs; gi[5]=a5*invs; gi[6]=a6*invs; gi[7]=a7*invs;
    }
}

// ---------------------------------------------------------------------------
// Kernel C: final MLP, 8 rows/CTA, 512 threads, K-split partials.
// ---------------------------------------------------------------------------
#define BTILE 8
#define C_AT   0
#define C_P    2176
#define C_H1   (2176 + 5120)
#define C_Q    (2176 + 5120 + 3072)
#define C_R    (2176 + 5120 + 3072 + 5120)
#define SMEMC_BYTES ((2176 + 5120 + 3072 + 5120 + 32) * 4)

__global__ void __launch_bounds__(512, 2)
din_mlp_kernel(const int* __restrict__ tgt,
               const int* __restrict__ sf,
               const float* __restrict__ dense,
               const float* __restrict__ item_table,
               const float* __restrict__ user_table,
               const float* __restrict__ ctx_table,
               const float* __restrict__ w1, const float* __restrict__ b1,
               const float* __restrict__ w2, const float* __restrict__ b2,
               const float* __restrict__ ow, const float* __restrict__ ob,
               float* __restrict__ out)
{
    extern __shared__ float smc[];
    float* At  = smc + C_AT;
    float* P   = smc + C_P;
    float* H1t = smc + C_H1;
    float* Qp  = smc + C_Q;
    float* R   = smc + C_R;

    const int b0   = blockIdx.x * BTILE;
    const int tid  = threadIdx.x;
    const int lane = tid & 31;

    for (int i = tid; i < 272 * BTILE; i += 512) {
        int bb = i & (BTILE - 1);
        int k  = i / BTILE;
        int gb = b0 + bb;
        float v;
        if (k < 64)        v = user_table[(long)sf[gb * 2] * 64 + k];
        else if (k < 128)  v = ctx_table[(long)sf[gb * 2 + 1] * 64 + (k - 64)];
        else if (k < 192)  v = item_table[(long)tgt[gb] * 64 + (k - 128)];
        else if (k < 256)  v = g_interest[(long)gb * 64 + (k - 192)];
        else               v = dense[gb * 16 + (k - 256)];
        At[k * BTILE + bb] = v;
    }
    __syncthreads();

    {
        const int n  = tid & 255;
        const int ks = tid >> 8;
        const int k0 = ks * 136;
        float2 acc[4];
        #pragma unroll
        for (int p = 0; p < 4; ++p) acc[p] = make_float2(0.f, 0.f);
        #pragma unroll 4
        for (int k = k0; k < k0 + 136; ++k) {
            float wv = w1[k * 256 + n];
            float2 bb = make_float2(wv, wv);
            const float4* ar4 = (const float4*)(At + k * BTILE);
            float4 aA = ar4[0];
            float4 aB = ar4[1];
            acc[0] = fma2(make_float2(aA.x, aA.y), bb, acc[0]);
            acc[1] = fma2(make_float2(aA.z, aA.w), bb, acc[1]);
            acc[2] = fma2(make_float2(aB.x, aB.y), bb, acc[2]);
            acc[3] = fma2(make_float2(aB.z, aB.w), bb, acc[3]);
        }
        float* pr = P + tid * 10;
        #pragma unroll
        for (int p = 0; p < 4; ++p) *(float2*)(pr + 2 * p) = acc[p];
    }
    __syncthreads();

    if (tid < 256) {
        float bias = b1[tid];
        const float* p0 = P + tid * 10;
        const float* p1 = P + (tid + 256) * 10;
        #pragma unroll
        for (int p = 0; p < 4; ++p) {
            float2 x = *(const float2*)(p0 + 2 * p);
            float2 y = *(const float2*)(p1 + 2 * p);
            float2 r = make_float2(fmaxf(x.x + y.x + bias, 0.f),
                                   fmaxf(x.y + y.y + bias, 0.f));
            *(float2*)(H1t + tid * 12 + 2 * p) = r;
        }
    }
    __syncthreads();

    {
        const int n  = tid & 127;
        const int ks = tid >> 7;
        const int k0 = ks * 64;
        float2 acc[4];
        #pragma unroll
        for (int p = 0; p < 4; ++p) acc[p] = make_float2(0.f, 0.f);
        #pragma unroll 4
        for (int k = k0; k < k0 + 64; ++k) {
            float wv = w2[k * 128 + n];
            float2 bb = make_float2(wv, wv);
            const float4* hr4 = (const float4*)(H1t + k * 12);
            float4 aA = hr4[0];
            float4 aB = hr4[1];
            acc[0] = fma2(make_float2(aA.x, aA.y), bb, acc[0]);
            acc[1] = fma2(make_float2(aA.z, aA.w), bb, acc[1]);
            acc[2] = fma2(make_float2(aB.x, aB.y), bb, acc[2]);
            acc[3] = fma2(make_float2(aB.z, aB.w), bb, acc[3]);
        }
        float* qr = Qp + tid * 10;
        #pragma unroll
        for (int p = 0; p < 4; ++p) *(float2*)(qr + 2 * p) = acc[p];
    }
    __syncthreads();

    if (tid < 128) {
        const int n = tid;
        float bias = b2[n];
        float owl  = ow[n];
        float s[8];
        #pragma unroll
        for (int m = 0; m < 8; ++m) {
            float v = Qp[(n)       * 10 + m]
                    + Qp[(n + 128) * 10 + m]
                    + Qp[(n + 256) * 10 + m]
                    + Qp[(n + 384) * 10 + m];
            s[m] = fmaxf(v + bias, 0.f) * owl;
        }
        #pragma unroll
        for (int off = 16; off > 0; off >>= 1) {
            #pragma unroll
            for (int m = 0; m < 8; ++m)
                s[m] += __shfl_xor_sync(0xffffffffu, s[m], off);
        }
        if (lane == 0) {
            int w = tid >> 5;
            #pragma unroll
            for (int m = 0; m < 8; ++m) R[w * 8 + m] = s[m];
        }
    }
    __syncthreads();
    if (tid < BTILE) {
        float s = R[tid] + R[8 + tid] + R[16 + tid] + R[24 + tid] + ob[0];
        out[b0 + tid] = s;
    }
}

// ---------------------------------------------------------------------------
extern "C" void kernel_launch(void* const* d_in, const int* in_sizes, int n_in,
                              void* d_out, int out_size)
{
    const int*   tgt   = (const int*)d_in[0];
    const int*   hist  = (const int*)d_in[1];
    const int*   mask  = (const int*)d_in[2];
    const int*   sf    = (const int*)d_in[3];
    const float* dense = (const float*)d_in[4];
    const float* item_table = (const float*)d_in[5];
    const float* user_table = (const float*)d_in[6];
    const float* ctx_table  = (const float*)d_in[7];
    const float* att_w1 = (const float*)d_in[8];
    const float* att_b1 = (const float*)d_in[9];
    const float* att_w2 = (const float*)d_in[10];
    const float* att_b2 = (const float*)d_in[11];
    const float* att_wo = (const float*)d_in[12];
    const float* att_bo = (const float*)d_in[13];
    const float* mlp_w1 = (const float*)d_in[14];
    const float* mlp_b1 = (const float*)d_in[15];
    const float* mlp_w2 = (const float*)d_in[16];
    const float* mlp_b2 = (const float*)d_in[17];
    const float* out_w  = (const float*)d_in[18];
    const float* out_b  = (const float*)d_in[19];
    float*       out    = (float*)d_out;

    cudaFuncSetAttribute(din_scores_kernel, cudaFuncAttributeMaxDynamicSharedMemorySize, SMEMA_BYTES);
    cudaFuncSetAttribute(din_mlp_kernel,    cudaFuncAttributeMaxDynamicSharedMemorySize, SMEMC_BYTES);

    din_fold_kernel<<<B_ROWS, 256>>>(tgt, item_table, att_w1, att_b1);

    din_scores_kernel<<<B_ROWS * 2, 256, SMEMA_BYTES>>>(
        tgt, hist, mask, item_table, att_w2, att_b2, att_wo, att_bo);

    din_softmax_kernel<<<B_ROWS, 256>>>(hist, item_table);

    din_mlp_kernel<<<B_ROWS / BTILE, 512, SMEMC_BYTES>>>(
        tgt, sf, dense, item_table, user_table, ctx_table,
        mlp_w1, mlp_b1, mlp_w2, mlp_b2, out_w, out_b, out);
}

// round 10
// speedup vs baseline: 1.5779x; 1.5779x over previous
#include <cuda_runtime.h>
#include <cuda_bf16.h>
#include <cstdint>

// ---------------------------------------------------------------------------
// DIN forward.
//  Kernel F: fold per-b attention weights -> g_w12t[b][j][k], g_qc[b][j]
//  Kernel A: scores via mma.sync bf16 m16n8k16, 3-way hi/lo split,
//            packed-bf16 smem (65KB) -> 3 CTAs/SM
//  Kernel B: softmax + interest
//  Kernel C: final MLP (fp32, k-split)
// ---------------------------------------------------------------------------

#define B_ROWS 4096
#define T_LEN  200
#define TPAD   224
#define E_DIM  64

__device__ float g_w12t[B_ROWS * 64 * 64];   // [b][j][k]
__device__ float g_qc[B_ROWS * 64];
__device__ float g_scores[B_ROWS * TPAD];
__device__ float g_interest[B_ROWS * E_DIM];

__device__ __forceinline__ float2 fma2(float2 a, float2 b, float2 c) {
    float2 d;
    asm("fma.rn.f32x2 %0, %1, %2, %3;"
        : "=l"(*(unsigned long long*)&d)
        : "l"(*(unsigned long long*)&a),
          "l"(*(unsigned long long*)&b),
          "l"(*(unsigned long long*)&c));
    return d;
}

// ---- bf16 split helpers ----
__device__ __forceinline__ void bsplit(float x, uint16_t& h, uint16_t& l) {
    __nv_bfloat16 bh = __float2bfloat16(x);
    float r = x - __bfloat162float(bh);
    __nv_bfloat16 bl = __float2bfloat16(r);
    h = *reinterpret_cast<uint16_t*>(&bh);
    l = *reinterpret_cast<uint16_t*>(&bl);
}
__device__ __forceinline__ uint32_t packu(uint16_t lo, uint16_t hi) {
    return (uint32_t)lo | ((uint32_t)hi << 16);
}
// split a pair (even k, odd k) -> packed hi word + packed lo word
__device__ __forceinline__ void bsplit2(float e, float o, uint32_t& wh, uint32_t& wl) {
    uint16_t eh, el, oh, ol;
    bsplit(e, eh, el);
    bsplit(o, oh, ol);
    wh = packu(eh, oh);
    wl = packu(el, ol);
}

// D += A*B  (m16n8k16, A row-major, B col-major, bf16 in, f32 acc)
__device__ __forceinline__ void mmabf(float* d, const uint32_t* a, const uint32_t* b) {
    asm volatile(
        "mma.sync.aligned.m16n8k16.row.col.f32.bf16.bf16.f32 "
        "{%0,%1,%2,%3}, {%4,%5,%6,%7}, {%8,%9}, {%0,%1,%2,%3};"
        : "+f"(d[0]), "+f"(d[1]), "+f"(d[2]), "+f"(d[3])
        : "r"(a[0]), "r"(a[1]), "r"(a[2]), "r"(a[3]), "r"(b[0]), "r"(b[1]));
}

// ---------------------------------------------------------------------------
// Kernel F: fold weights per b, store transposed [j][k].
// ---------------------------------------------------------------------------
__global__ void __launch_bounds__(256, 4)
din_fold_kernel(const int* __restrict__ tgt,
                const float* __restrict__ item_table,
                const float* __restrict__ w1, const float* __restrict__ b1)
{
    __shared__ float Q[64];
    __shared__ float SM[64 * 65];
    const int b   = blockIdx.x;
    const int tid = threadIdx.x;

    if (tid < 64) Q[tid] = item_table[(long)tgt[b] * 64 + tid];
    __syncthreads();

    for (int i = tid; i < 4096; i += 256) {
        int k = i >> 6, j = i & 63;
        SM[k * 65 + j] = w1[i] + w1[8192 + i] + Q[k] * w1[12288 + i];
    }
    __syncthreads();
    for (int i = tid; i < 4096; i += 256) {
        int j = i >> 6, k = i & 63;
        g_w12t[(long)b * 4096 + i] = SM[k * 65 + j];
    }
    if (tid < 64) {
        float s = b1[tid];
        #pragma unroll 8
        for (int e = 0; e < 64; ++e)
            s += Q[e] * (w1[4096 + e * 64 + tid] - w1[8192 + e * 64 + tid]);
        g_qc[b * 64 + tid] = s;
    }
}

// ---------------------------------------------------------------------------
// Kernel A: scores via mma.sync bf16 k16. grid = 2*B, 256 thr (8 warps x m16).
// All operands packed bf16 pairs (u32 words, 32 words/row, stride 36 -> CF).
// smem (u32 words):
//   KH/H1H[128][36] @0     | KL/H1L[128][36] @4608
//   W12H[64][36] @9216     | W12L[64][36] @11520
//   W2H[32][36]  @13824    | W2L[32][36]  @14976
//   QC[64] @16128 | B2[32] @16192 | WO[32] @16224   -> 16256 w = 65KB
// ---------------------------------------------------------------------------
#define SA_KH    0
#define SA_KL    4608
#define SA_W12H  9216
#define SA_W12L  11520
#define SA_W2H   13824
#define SA_W2L   14976
#define SA_QC    16128
#define SA_B2    16192
#define SA_WO    16224
#define SMEMA_WORDS 16256
#define SMEMA_BYTES (SMEMA_WORDS * 4)

__global__ void __launch_bounds__(256, 3)
din_scores_kernel(const int* __restrict__ tgt,
                  const int* __restrict__ hist,
                  const int* __restrict__ mask,
                  const float* __restrict__ item_table,
                  const float* __restrict__ w2, const float* __restrict__ b2,
                  const float* __restrict__ wo, const float* __restrict__ bo)
{
    extern __shared__ uint32_t smu[];
    uint32_t* KH   = smu + SA_KH;     // aliased by H1H after A-frag hoist
    uint32_t* KL   = smu + SA_KL;     // aliased by H1L
    uint32_t* W12H = smu + SA_W12H;
    uint32_t* W12L = smu + SA_W12L;
    uint32_t* W2H  = smu + SA_W2H;
    uint32_t* W2L  = smu + SA_W2L;
    float*    QC   = (float*)(smu + SA_QC);
    float*    B2S  = (float*)(smu + SA_B2);
    float*    WOS  = (float*)(smu + SA_WO);

    const int b    = blockIdx.x >> 1;
    const int t0   = (blockIdx.x & 1) * 128;
    const int tid  = threadIdx.x;
    const int lane = tid & 31;
    const int wid  = tid >> 5;      // 0..7
    const int gid  = lane >> 2;     // 0..7
    const int tig  = lane & 3;      // 0..3

    // ---- stage operands ----
    // keys -> packed bf16 hi/lo
    for (int i = tid; i < 128 * 16; i += 256) {
        int f4 = i & 15;
        int m  = i >> 4;
        int tg = t0 + m;
        float4 v = make_float4(0.f, 0.f, 0.f, 0.f);
        if (tg < T_LEN) {
            int row = hist[b * T_LEN + tg];
            v = *(const float4*)(item_table + (long)row * E_DIM + 4 * f4);
        }
        uint32_t h0, l0, h1, l1;
        bsplit2(v.x, v.y, h0, l0);
        bsplit2(v.z, v.w, h1, l1);
        KH[m * 36 + 2 * f4]     = h0;
        KH[m * 36 + 2 * f4 + 1] = h1;
        KL[m * 36 + 2 * f4]     = l0;
        KL[m * 36 + 2 * f4 + 1] = l1;
    }
    // W12T[j][k] pairs
    for (int i = tid; i < 2048; i += 256) {
        int j = i >> 5, w = i & 31;
        float2 v = *(const float2*)(g_w12t + (long)b * 4096 + j * 64 + 2 * w);
        uint32_t h, l;
        bsplit2(v.x, v.y, h, l);
        W12H[j * 36 + w] = h;
        W12L[j * 36 + w] = l;
    }
    // W2T[n][k=j] pairs from w2[j][n]
    for (int i = tid; i < 1024; i += 256) {
        int n = i & 31, w = i >> 5;
        float e = w2[(2 * w) * 32 + n];
        float o = w2[(2 * w + 1) * 32 + n];
        uint32_t h, l;
        bsplit2(e, o, h, l);
        W2H[n * 36 + w] = h;
        W2L[n * 36 + w] = l;
    }
    if (tid < 64) QC[tid] = g_qc[b * 64 + tid];
    if (tid < 32) { B2S[tid] = b2[tid]; WOS[tid] = wo[tid]; }
    __syncthreads();

    const int mb = wid * 16;

    // ---- GEMM1: H1[m][j] = relu(KEYS @ W12T^T + qc) ----
    {
        // hoist A fragments (4 k-chunks of 16) into registers
        uint32_t ah[4][4], al[4][4];
        #pragma unroll
        for (int kc = 0; kc < 4; ++kc) {
            int a0 = (mb + gid) * 36 + kc * 8 + tig;
            int a1 = (mb + gid + 8) * 36 + kc * 8 + tig;
            ah[kc][0] = KH[a0]; ah[kc][1] = KH[a1];
            ah[kc][2] = KH[a0 + 4]; ah[kc][3] = KH[a1 + 4];
            al[kc][0] = KL[a0]; al[kc][1] = KL[a1];
            al[kc][2] = KL[a0 + 4]; al[kc][3] = KL[a1 + 4];
        }
        __syncthreads();   // KEYS dead; smem becomes H1

        #pragma unroll
        for (int nt = 0; nt < 8; ++nt) {
            float acc[4] = {0.f, 0.f, 0.f, 0.f};
            #pragma unroll
            for (int kc = 0; kc < 4; ++kc) {
                const int boff = (nt * 8 + gid) * 36 + kc * 8 + tig;
                uint32_t bh[2], bl[2];
                bh[0] = W12H[boff]; bh[1] = W12H[boff + 4];
                bl[0] = W12L[boff]; bl[1] = W12L[boff + 4];
                mmabf(acc, ah[kc], bh);
                mmabf(acc, ah[kc], bl);
                mmabf(acc, al[kc], bh);
            }
            int j0 = nt * 8 + 2 * tig;
            float q0 = QC[j0], q1 = QC[j0 + 1];
            float v0 = fmaxf(acc[0] + q0, 0.f);
            float v1 = fmaxf(acc[1] + q1, 0.f);
            float v2 = fmaxf(acc[2] + q0, 0.f);
            float v3 = fmaxf(acc[3] + q1, 0.f);
            uint32_t h01, l01, h23, l23;
            bsplit2(v0, v1, h01, l01);
            bsplit2(v2, v3, h23, l23);
            KH[(mb + gid) * 36 + nt * 4 + tig]     = h01;  // H1H
            KL[(mb + gid) * 36 + nt * 4 + tig]     = l01;  // H1L
            KH[(mb + gid + 8) * 36 + nt * 4 + tig] = h23;
            KL[(mb + gid + 8) * 36 + nt * 4 + tig] = l23;
        }
    }
    __syncwarp();   // H1 rows are warp-private; cross-lane visibility only

    // ---- GEMM2: scores = reduce_n relu(H1 @ W2T^T + b2)*wo ----
    {
        uint32_t ah[4][4], al[4][4];
        #pragma unroll
        for (int kc = 0; kc < 4; ++kc) {
            int a0 = (mb + gid) * 36 + kc * 8 + tig;
            int a1 = (mb + gid + 8) * 36 + kc * 8 + tig;
            ah[kc][0] = KH[a0]; ah[kc][1] = KH[a1];
            ah[kc][2] = KH[a0 + 4]; ah[kc][3] = KH[a1 + 4];
            al[kc][0] = KL[a0]; al[kc][1] = KL[a1];
            al[kc][2] = KL[a0 + 4]; al[kc][3] = KL[a1 + 4];
        }
        float srow0 = 0.f, srow8 = 0.f;
        #pragma unroll
        for (int nt = 0; nt < 4; ++nt) {
            float acc[4] = {0.f, 0.f, 0.f, 0.f};
            #pragma unroll
            for (int kc = 0; kc < 4; ++kc) {
                const int boff = (nt * 8 + gid) * 36 + kc * 8 + tig;
                uint32_t bh[2], bl[2];
                bh[0] = W2H[boff]; bh[1] = W2H[boff + 4];
                bl[0] = W2L[boff]; bl[1] = W2L[boff + 4];
                mmabf(acc, ah[kc], bh);
                mmabf(acc, ah[kc], bl);
                mmabf(acc, al[kc], bh);
            }
            int n0 = nt * 8 + 2 * tig;
            float bb0 = B2S[n0], bb1 = B2S[n0 + 1];
            float w0 = WOS[n0],  w1v = WOS[n0 + 1];
            srow0 += fmaxf(acc[0] + bb0, 0.f) * w0 + fmaxf(acc[1] + bb1, 0.f) * w1v;
            srow8 += fmaxf(acc[2] + bb0, 0.f) * w0 + fmaxf(acc[3] + bb1, 0.f) * w1v;
        }
        srow0 += __shfl_xor_sync(0xffffffffu, srow0, 1);
        srow0 += __shfl_xor_sync(0xffffffffu, srow0, 2);
        srow8 += __shfl_xor_sync(0xffffffffu, srow8, 1);
        srow8 += __shfl_xor_sync(0xffffffffu, srow8, 2);

        if (tig == 0) {
            float bos = bo[0];
            int tg0 = t0 + mb + gid;
            int tg8 = tg0 + 8;
            if (tg0 < T_LEN)
                g_scores[b * TPAD + tg0] = mask[b * T_LEN + tg0] ? srow0 + bos : -1e9f;
            else if (tg0 < TPAD)
                g_scores[b * TPAD + tg0] = -1e9f;
            if (tg8 < T_LEN)
                g_scores[b * TPAD + tg8] = mask[b * T_LEN + tg8] ? srow8 + bos : -1e9f;
            else if (tg8 < TPAD)
                g_scores[b * TPAD + tg8] = -1e9f;
        }
    }
}

// ---------------------------------------------------------------------------
// Kernel B: softmax over 224 scores + interest vector (re-gather keys).
// ---------------------------------------------------------------------------
__global__ void __launch_bounds__(256, 8)
din_softmax_kernel(const int* __restrict__ hist,
                   const float* __restrict__ item_table)
{
    __shared__ float SC[TPAD];
    __shared__ float WG[TPAD];
    __shared__ float RED[8];
    __shared__ float SV[2];

    const int b    = blockIdx.x;
    const int tid  = threadIdx.x;
    const int lane = tid & 31;
    const int warp = tid >> 5;

    float s = (tid < TPAD) ? g_scores[b * TPAD + tid] : -3.4e38f;
    if (tid < TPAD) SC[tid] = s;

    float m = s;
    #pragma unroll
    for (int off = 16; off > 0; off >>= 1)
        m = fmaxf(m, __shfl_xor_sync(0xffffffffu, m, off));
    if (lane == 0) RED[warp] = m;
    __syncthreads();
    if (warp == 0) {
        float mm = (lane < 7) ? RED[lane] : -3.4e38f;
        #pragma unroll
        for (int off = 4; off > 0; off >>= 1)
            mm = fmaxf(mm, __shfl_xor_sync(0xffffffffu, mm, off));
        if (lane == 0) SV[0] = mm;
    }
    __syncthreads();

    float e = 0.f;
    if (tid < TPAD) {
        e = expf(SC[tid] - SV[0]);
        WG[tid] = e;
    }
    #pragma unroll
    for (int off = 16; off > 0; off >>= 1)
        e += __shfl_xor_sync(0xffffffffu, e, off);
    if (lane == 0) RED[warp] = e;
    __syncthreads();
    if (warp == 0) {
        float t2 = (lane < 7) ? RED[lane] : 0.f;
        #pragma unroll
        for (int off = 4; off > 0; off >>= 1)
            t2 += __shfl_xor_sync(0xffffffffu, t2, off);
        if (lane == 0) SV[1] = t2;
    }
    __syncthreads();

    const int e0 = warp * 8;
    float a0=0.f,a1=0.f,a2=0.f,a3=0.f,a4=0.f,a5=0.f,a6=0.f,a7=0.f;
    #pragma unroll
    for (int i = 0; i < 7; ++i) {
        int t = lane + 32 * i;
        float wv = WG[t];
        if (t < T_LEN) {
            int row = hist[b * T_LEN + t];
            const float* kp = item_table + (long)row * E_DIM + e0;
            float4 va = *(const float4*)(kp);
            float4 vb = *(const float4*)(kp + 4);
            a0 += wv * va.x; a1 += wv * va.y; a2 += wv * va.z; a3 += wv * va.w;
            a4 += wv * vb.x; a5 += wv * vb.y; a6 += wv * vb.z; a7 += wv * vb.w;
        }
    }
    #pragma unroll
    for (int off = 16; off > 0; off >>= 1) {
        a0 += __shfl_xor_sync(0xffffffffu, a0, off);
        a1 += __shfl_xor_sync(0xffffffffu, a1, off);
        a2 += __shfl_xor_sync(0xffffffffu, a2, off);
        a3 += __shfl_xor_sync(0xffffffffu, a3, off);
        a4 += __shfl_xor_sync(0xffffffffu, a4, off);
        a5 += __shfl_xor_sync(0xffffffffu, a5, off);
        a6 += __shfl_xor_sync(0xffffffffu, a6, off);
        a7 += __shfl_xor_sync(0xffffffffu, a7, off);
    }
    if (lane == 0) {
        float invs = 1.0f / SV[1];
        float* gi = g_interest + (long)b * E_DIM + e0;
        gi[0]=a0*invs; gi[1]=a1*invs; gi[2]=a2*invs; gi[3]=a3*invs;
        gi[4]=a4*invs; gi[5]=a5*invs; gi[6]=a6*invs; gi[7]=a7*invs;
    }
}

// ---------------------------------------------------------------------------
// Kernel C: final MLP, 8 rows/CTA, 512 threads, K-split partials.
// ---------------------------------------------------------------------------
#define BTILE 8
#define C_AT   0
#define C_P    2176
#define C_H1   (2176 + 5120)
#define C_Q    (2176 + 5120 + 3072)
#define C_R    (2176 + 5120 + 3072 + 5120)
#define SMEMC_BYTES ((2176 + 5120 + 3072 + 5120 + 32) * 4)

__global__ void __launch_bounds__(512, 2)
din_mlp_kernel(const int* __restrict__ tgt,
               const int* __restrict__ sf,
               const float* __restrict__ dense,
               const float* __restrict__ item_table,
               const float* __restrict__ user_table,
               const float* __restrict__ ctx_table,
               const float* __restrict__ w1, const float* __restrict__ b1,
               const float* __restrict__ w2, const float* __restrict__ b2,
               const float* __restrict__ ow, const float* __restrict__ ob,
               float* __restrict__ out)
{
    extern __shared__ float smc[];
    float* At  = smc + C_AT;
    float* P   = smc + C_P;
    float* H1t = smc + C_H1;
    float* Qp  = smc + C_Q;
    float* R   = smc + C_R;

    const int b0   = blockIdx.x * BTILE;
    const int tid  = threadIdx.x;
    const int lane = tid & 31;

    for (int i = tid; i < 272 * BTILE; i += 512) {
        int bb = i & (BTILE - 1);
        int k  = i / BTILE;
        int gb = b0 + bb;
        float v;
        if (k < 64)        v = user_table[(long)sf[gb * 2] * 64 + k];
        else if (k < 128)  v = ctx_table[(long)sf[gb * 2 + 1] * 64 + (k - 64)];
        else if (k < 192)  v = item_table[(long)tgt[gb] * 64 + (k - 128)];
        else if (k < 256)  v = g_interest[(long)gb * 64 + (k - 192)];
        else               v = dense[gb * 16 + (k - 256)];
        At[k * BTILE + bb] = v;
    }
    __syncthreads();

    {
        const int n  = tid & 255;
        const int ks = tid >> 8;
        const int k0 = ks * 136;
        float2 acc[4];
        #pragma unroll
        for (int p = 0; p < 4; ++p) acc[p] = make_float2(0.f, 0.f);
        #pragma unroll 4
        for (int k = k0; k < k0 + 136; ++k) {
            float wv = w1[k * 256 + n];
            float2 bb = make_float2(wv, wv);
            const float4* ar4 = (const float4*)(At + k * BTILE);
            float4 aA = ar4[0];
            float4 aB = ar4[1];
            acc[0] = fma2(make_float2(aA.x, aA.y), bb, acc[0]);
            acc[1] = fma2(make_float2(aA.z, aA.w), bb, acc[1]);
            acc[2] = fma2(make_float2(aB.x, aB.y), bb, acc[2]);
            acc[3] = fma2(make_float2(aB.z, aB.w), bb, acc[3]);
        }
        float* pr = P + tid * 10;
        #pragma unroll
        for (int p = 0; p < 4; ++p) *(float2*)(pr + 2 * p) = acc[p];
    }
    __syncthreads();

    if (tid < 256) {
        float bias = b1[tid];
        const float* p0 = P + tid * 10;
        const float* p1 = P + (tid + 256) * 10;
        #pragma unroll
        for (int p = 0; p < 4; ++p) {
            float2 x = *(const float2*)(p0 + 2 * p);
            float2 y = *(const float2*)(p1 + 2 * p);
            float2 r = make_float2(fmaxf(x.x + y.x + bias, 0.f),
                                   fmaxf(x.y + y.y + bias, 0.f));
            *(float2*)(H1t + tid * 12 + 2 * p) = r;
        }
    }
    __syncthreads();

    {
        const int n  = tid & 127;
        const int ks = tid >> 7;
        const int k0 = ks * 64;
        float2 acc[4];
        #pragma unroll
        for (int p = 0; p < 4; ++p) acc[p] = make_float2(0.f, 0.f);
        #pragma unroll 4
        for (int k = k0; k < k0 + 64; ++k) {
            float wv = w2[k * 128 + n];
            float2 bb = make_float2(wv, wv);
            const float4* hr4 = (const float4*)(H1t + k * 12);
            float4 aA = hr4[0];
            float4 aB = hr4[1];
            acc[0] = fma2(make_float2(aA.x, aA.y), bb, acc[0]);
            acc[1] = fma2(make_float2(aA.z, aA.w), bb, acc[1]);
            acc[2] = fma2(make_float2(aB.x, aB.y), bb, acc[2]);
            acc[3] = fma2(make_float2(aB.z, aB.w), bb, acc[3]);
        }
        float* qr = Qp + tid * 10;
        #pragma unroll
        for (int p = 0; p < 4; ++p) *(float2*)(qr + 2 * p) = acc[p];
    }
    __syncthreads();

    if (tid < 128) {
        const int n = tid;
        float bias = b2[n];
        float owl  = ow[n];
        float s[8];
        #pragma unroll
        for (int m = 0; m < 8; ++m) {
            float v = Qp[(n)       * 10 + m]
                    + Qp[(n + 128) * 10 + m]
                    + Qp[(n + 256) * 10 + m]
                    + Qp[(n + 384) * 10 + m];
            s[m] = fmaxf(v + bias, 0.f) * owl;
        }
        #pragma unroll
        for (int off = 16; off > 0; off >>= 1) {
            #pragma unroll
            for (int m = 0; m < 8; ++m)
                s[m] += __shfl_xor_sync(0xffffffffu, s[m], off);
        }
        if (lane == 0) {
            int w = tid >> 5;
            #pragma unroll
            for (int m = 0; m < 8; ++m) R[w * 8 + m] = s[m];
        }
    }
    __syncthreads();
    if (tid < BTILE) {
        float s = R[tid] + R[8 + tid] + R[16 + tid] + R[24 + tid] + ob[0];
        out[b0 + tid] = s;
    }
}

// ---------------------------------------------------------------------------
extern "C" void kernel_launch(void* const* d_in, const int* in_sizes, int n_in,
                              void* d_out, int out_size)
{
    const int*   tgt   = (const int*)d_in[0];
    const int*   hist  = (const int*)d_in[1];
    const int*   mask  = (const int*)d_in[2];
    const int*   sf    = (const int*)d_in[3];
    const float* dense = (const float*)d_in[4];
    const float* item_table = (const float*)d_in[5];
    const float* user_table = (const float*)d_in[6];
    const float* ctx_table  = (const float*)d_in[7];
    const float* att_w1 = (const float*)d_in[8];
    const float* att_b1 = (const float*)d_in[9];
    const float* att_w2 = (const float*)d_in[10];
    const float* att_b2 = (const float*)d_in[11];
    const float* att_wo = (const float*)d_in[12];
    const float* att_bo = (const float*)d_in[13];
    const float* mlp_w1 = (const float*)d_in[14];
    const float* mlp_b1 = (const float*)d_in[15];
    const float* mlp_w2 = (const float*)d_in[16];
    const float* mlp_b2 = (const float*)d_in[17];
    const float* out_w  = (const float*)d_in[18];
    const float* out_b  = (const float*)d_in[19];
    float*       out    = (float*)d_out;

    cudaFuncSetAttribute(din_scores_kernel, cudaFuncAttributeMaxDynamicSharedMemorySize, SMEMA_BYTES);
    cudaFuncSetAttribute(din_mlp_kernel,    cudaFuncAttributeMaxDynamicSharedMemorySize, SMEMC_BYTES);

    din_fold_kernel<<<B_ROWS, 256>>>(tgt, item_table, att_w1, att_b1);

    din_scores_kernel<<<B_ROWS * 2, 256, SMEMA_BYTES>>>(
        tgt, hist, mask, item_table, att_w2, att_b2, att_wo, att_bo);

    din_softmax_kernel<<<B_ROWS, 256>>>(hist, item_table);

    din_mlp_kernel<<<B_ROWS / BTILE, 512, SMEMC_BYTES>>>(
        tgt, sf, dense, item_table, user_table, ctx_table,
        mlp_w1, mlp_b1, mlp_w2, mlp_b2, out_w, out_b, out);
}

// round 11
// speedup vs baseline: 1.8734x; 1.1873x over previous
#include <cuda_runtime.h>
#include <cuda_bf16.h>
#include <cstdint>

// ---------------------------------------------------------------------------
// DIN forward.
//  Kernel P: pre-split item_table + w2 into packed bf16 hi/lo pairs
//  Kernel F: fold per-b attention weights -> packed g_w12H/L, g_qc
//  Kernel A: scores via mma.sync bf16 m16n8k16, 3-pass hi/lo; staging = copies
//  Kernel B: softmax + interest
//  Kernel C: final MLP (fp32, k-split)
// ---------------------------------------------------------------------------

#define B_ROWS 4096
#define T_LEN  200
#define TPAD   224
#define E_DIM  64
#define VOCAB_ITEM 100000

__device__ uint32_t g_keyH[VOCAB_ITEM * 32];    // packed bf16-hi pairs per row
__device__ uint32_t g_keyL[VOCAB_ITEM * 32];    // packed bf16-lo pairs
__device__ uint32_t g_w12H[B_ROWS * 2048];      // [b][j][w] packed pairs
__device__ uint32_t g_w12L[B_ROWS * 2048];
__device__ uint32_t g_w2H[1024];                // [n][w]
__device__ uint32_t g_w2L[1024];
__device__ float g_qc[B_ROWS * 64];
__device__ float g_scores[B_ROWS * TPAD];
__device__ float g_interest[B_ROWS * E_DIM];

__device__ __forceinline__ float2 fma2(float2 a, float2 b, float2 c) {
    float2 d;
    asm("fma.rn.f32x2 %0, %1, %2, %3;"
        : "=l"(*(unsigned long long*)&d)
        : "l"(*(unsigned long long*)&a),
          "l"(*(unsigned long long*)&b),
          "l"(*(unsigned long long*)&c));
    return d;
}

// ---- bf16 split helpers ----
__device__ __forceinline__ void bsplit(float x, uint16_t& h, uint16_t& l) {
    __nv_bfloat16 bh = __float2bfloat16(x);
    float r = x - __bfloat162float(bh);
    __nv_bfloat16 bl = __float2bfloat16(r);
    h = *reinterpret_cast<uint16_t*>(&bh);
    l = *reinterpret_cast<uint16_t*>(&bl);
}
__device__ __forceinline__ uint32_t packu(uint16_t lo, uint16_t hi) {
    return (uint32_t)lo | ((uint32_t)hi << 16);
}
__device__ __forceinline__ void bsplit2(float e, float o, uint32_t& wh, uint32_t& wl) {
    uint16_t eh, el, oh, ol;
    bsplit(e, eh, el);
    bsplit(o, oh, ol);
    wh = packu(eh, oh);
    wl = packu(el, ol);
}

// D += A*B  (m16n8k16, A row-major, B col-major, bf16 in, f32 acc)
__device__ __forceinline__ void mmabf(float* d, const uint32_t* a, const uint32_t* b) {
    asm volatile(
        "mma.sync.aligned.m16n8k16.row.col.f32.bf16.bf16.f32 "
        "{%0,%1,%2,%3}, {%4,%5,%6,%7}, {%8,%9}, {%0,%1,%2,%3};"
        : "+f"(d[0]), "+f"(d[1]), "+f"(d[2]), "+f"(d[3])
        : "r"(a[0]), "r"(a[1]), "r"(a[2]), "r"(a[3]), "r"(b[0]), "r"(b[1]));
}

// ---------------------------------------------------------------------------
// Kernel P: pre-split item_table rows (and w2) into packed bf16 hi/lo pairs.
// ---------------------------------------------------------------------------
__global__ void __launch_bounds__(256)
din_pack_kernel(const float* __restrict__ item_table,
                const float* __restrict__ w2)
{
    long i = (long)blockIdx.x * 256 + threadIdx.x;   // pair index
    if (i < (long)VOCAB_ITEM * 32) {
        float2 v = ((const float2*)item_table)[i];
        uint32_t h, l;
        bsplit2(v.x, v.y, h, l);
        g_keyH[i] = h;
        g_keyL[i] = l;
    }
    if (i < 1024) {                                  // w2: n-major packed pairs
        int n = (int)i & 31, w = (int)i >> 5;
        float e = w2[(2 * w) * 32 + n];
        float o = w2[(2 * w + 1) * 32 + n];
        uint32_t h, l;
        bsplit2(e, o, h, l);
        g_w2H[n * 32 + w] = h;
        g_w2L[n * 32 + w] = l;
    }
}

// ---------------------------------------------------------------------------
// Kernel F: fold weights per b -> packed bf16 hi/lo, transposed [j][k-pairs].
// ---------------------------------------------------------------------------
__global__ void __launch_bounds__(256, 4)
din_fold_kernel(const int* __restrict__ tgt,
                const float* __restrict__ item_table,
                const float* __restrict__ w1, const float* __restrict__ b1)
{
    __shared__ float Q[64];
    __shared__ float SM[64 * 65];
    const int b   = blockIdx.x;
    const int tid = threadIdx.x;

    if (tid < 64) Q[tid] = item_table[(long)tgt[b] * 64 + tid];
    __syncthreads();

    for (int i = tid; i < 4096; i += 256) {
        int k = i >> 6, j = i & 63;
        SM[k * 65 + j] = w1[i] + w1[8192 + i] + Q[k] * w1[12288 + i];
    }
    __syncthreads();
    for (int i = tid; i < 2048; i += 256) {
        int j = i >> 5, w = i & 31;
        float e = SM[(2 * w) * 65 + j];
        float o = SM[(2 * w + 1) * 65 + j];
        uint32_t h, l;
        bsplit2(e, o, h, l);
        g_w12H[(long)b * 2048 + i] = h;
        g_w12L[(long)b * 2048 + i] = l;
    }
    if (tid < 64) {
        float s = b1[tid];
        #pragma unroll 8
        for (int e = 0; e < 64; ++e)
            s += Q[e] * (w1[4096 + e * 64 + tid] - w1[8192 + e * 64 + tid]);
        g_qc[b * 64 + tid] = s;
    }
}

// ---------------------------------------------------------------------------
// Kernel A: scores via mma.sync bf16 k16. grid = 2*B, 256 thr (8 warps x m16).
// Staging = pure uint4 copies from pre-split globals. smem 65KB -> 3 CTAs/SM.
// ---------------------------------------------------------------------------
#define SA_KH    0
#define SA_KL    4608
#define SA_W12H  9216
#define SA_W12L  11520
#define SA_W2H   13824
#define SA_W2L   14976
#define SA_QC    16128
#define SA_B2    16192
#define SA_WO    16224
#define SMEMA_WORDS 16256
#define SMEMA_BYTES (SMEMA_WORDS * 4)

__global__ void __launch_bounds__(256, 3)
din_scores_kernel(const int* __restrict__ tgt,
                  const int* __restrict__ hist,
                  const int* __restrict__ mask,
                  const float* __restrict__ b2,
                  const float* __restrict__ wo, const float* __restrict__ bo)
{
    extern __shared__ uint32_t smu[];
    uint32_t* KH   = smu + SA_KH;     // aliased by H1H after A-frag hoist
    uint32_t* KL   = smu + SA_KL;     // aliased by H1L
    uint32_t* W12H = smu + SA_W12H;
    uint32_t* W12L = smu + SA_W12L;
    uint32_t* W2H  = smu + SA_W2H;
    uint32_t* W2L  = smu + SA_W2L;
    float*    QC   = (float*)(smu + SA_QC);
    float*    B2S  = (float*)(smu + SA_B2);
    float*    WOS  = (float*)(smu + SA_WO);

    const int b    = blockIdx.x >> 1;
    const int t0   = (blockIdx.x & 1) * 128;
    const int tid  = threadIdx.x;
    const int lane = tid & 31;
    const int wid  = tid >> 5;      // 0..7
    const int gid  = lane >> 2;     // 0..7
    const int tig  = lane & 3;      // 0..3

    // ---- stage operands (pure copies) ----
    {
        const uint4* HV = (const uint4*)g_keyH;
        const uint4* LV = (const uint4*)g_keyL;
        for (int i = tid; i < 128 * 8; i += 256) {
            int f = i & 7, m = i >> 3;
            int tg = t0 + m;
            uint4 h = make_uint4(0u, 0u, 0u, 0u);
            uint4 l = make_uint4(0u, 0u, 0u, 0u);
            if (tg < T_LEN) {
                int row = hist[b * T_LEN + tg];
                h = HV[row * 8 + f];
                l = LV[row * 8 + f];
            }
            *(uint4*)(KH + m * 36 + 4 * f) = h;
            *(uint4*)(KL + m * 36 + 4 * f) = l;
        }
        const uint4* WH = (const uint4*)(g_w12H + (long)b * 2048);
        const uint4* WL = (const uint4*)(g_w12L + (long)b * 2048);
        for (int i = tid; i < 64 * 8; i += 256) {
            int f = i & 7, j = i >> 3;
            *(uint4*)(W12H + j * 36 + 4 * f) = WH[i];
            *(uint4*)(W12L + j * 36 + 4 * f) = WL[i];
        }
        const uint4* VH = (const uint4*)g_w2H;
        const uint4* VL = (const uint4*)g_w2L;
        if (tid < 256) {
            int i = tid;
            int f = i & 7, n = i >> 3;
            *(uint4*)(W2H + n * 36 + 4 * f) = VH[i];
            *(uint4*)(W2L + n * 36 + 4 * f) = VL[i];
        }
    }
    if (tid < 64) QC[tid] = g_qc[b * 64 + tid];
    if (tid < 32) { B2S[tid] = b2[tid]; WOS[tid] = wo[tid]; }
    __syncthreads();

    const int mb = wid * 16;

    // ---- GEMM1: H1[m][j] = relu(KEYS @ W12T^T + qc) ----
    {
        uint32_t ah[4][4], al[4][4];
        #pragma unroll
        for (int kc = 0; kc < 4; ++kc) {
            int a0 = (mb + gid) * 36 + kc * 8 + tig;
            int a1 = (mb + gid + 8) * 36 + kc * 8 + tig;
            ah[kc][0] = KH[a0]; ah[kc][1] = KH[a1];
            ah[kc][2] = KH[a0 + 4]; ah[kc][3] = KH[a1 + 4];
            al[kc][0] = KL[a0]; al[kc][1] = KL[a1];
            al[kc][2] = KL[a0 + 4]; al[kc][3] = KL[a1 + 4];
        }
        __syncthreads();   // KEYS dead; smem becomes H1

        #pragma unroll
        for (int nt = 0; nt < 8; ++nt) {
            float acc[4] = {0.f, 0.f, 0.f, 0.f};
            #pragma unroll
            for (int kc = 0; kc < 4; ++kc) {
                const int boff = (nt * 8 + gid) * 36 + kc * 8 + tig;
                uint32_t bh[2], bl[2];
                bh[0] = W12H[boff]; bh[1] = W12H[boff + 4];
                bl[0] = W12L[boff]; bl[1] = W12L[boff + 4];
                mmabf(acc, ah[kc], bh);
                mmabf(acc, ah[kc], bl);
                mmabf(acc, al[kc], bh);
            }
            int j0 = nt * 8 + 2 * tig;
            float q0 = QC[j0], q1 = QC[j0 + 1];
            float v0 = fmaxf(acc[0] + q0, 0.f);
            float v1 = fmaxf(acc[1] + q1, 0.f);
            float v2 = fmaxf(acc[2] + q0, 0.f);
            float v3 = fmaxf(acc[3] + q1, 0.f);
            uint32_t h01, l01, h23, l23;
            bsplit2(v0, v1, h01, l01);
            bsplit2(v2, v3, h23, l23);
            KH[(mb + gid) * 36 + nt * 4 + tig]     = h01;  // H1H
            KL[(mb + gid) * 36 + nt * 4 + tig]     = l01;  // H1L
            KH[(mb + gid + 8) * 36 + nt * 4 + tig] = h23;
            KL[(mb + gid + 8) * 36 + nt * 4 + tig] = l23;
        }
    }
    __syncwarp();   // H1 rows are warp-private

    // ---- GEMM2: scores = reduce_n relu(H1 @ W2T^T + b2)*wo ----
    {
        uint32_t ah[4][4], al[4][4];
        #pragma unroll
        for (int kc = 0; kc < 4; ++kc) {
            int a0 = (mb + gid) * 36 + kc * 8 + tig;
            int a1 = (mb + gid + 8) * 36 + kc * 8 + tig;
            ah[kc][0] = KH[a0]; ah[kc][1] = KH[a1];
            ah[kc][2] = KH[a0 + 4]; ah[kc][3] = KH[a1 + 4];
            al[kc][0] = KL[a0]; al[kc][1] = KL[a1];
            al[kc][2] = KL[a0 + 4]; al[kc][3] = KL[a1 + 4];
        }
        float srow0 = 0.f, srow8 = 0.f;
        #pragma unroll
        for (int nt = 0; nt < 4; ++nt) {
            float acc[4] = {0.f, 0.f, 0.f, 0.f};
            #pragma unroll
            for (int kc = 0; kc < 4; ++kc) {
                const int boff = (nt * 8 + gid) * 36 + kc * 8 + tig;
                uint32_t bh[2], bl[2];
                bh[0] = W2H[boff]; bh[1] = W2H[boff + 4];
                bl[0] = W2L[boff]; bl[1] = W2L[boff + 4];
                mmabf(acc, ah[kc], bh);
                mmabf(acc, ah[kc], bl);
                mmabf(acc, al[kc], bh);
            }
            int n0 = nt * 8 + 2 * tig;
            float bb0 = B2S[n0], bb1 = B2S[n0 + 1];
            float w0 = WOS[n0],  w1v = WOS[n0 + 1];
            srow0 += fmaxf(acc[0] + bb0, 0.f) * w0 + fmaxf(acc[1] + bb1, 0.f) * w1v;
            srow8 += fmaxf(acc[2] + bb0, 0.f) * w0 + fmaxf(acc[3] + bb1, 0.f) * w1v;
        }
        srow0 += __shfl_xor_sync(0xffffffffu, srow0, 1);
        srow0 += __shfl_xor_sync(0xffffffffu, srow0, 2);
        srow8 += __shfl_xor_sync(0xffffffffu, srow8, 1);
        srow8 += __shfl_xor_sync(0xffffffffu, srow8, 2);

        if (tig == 0) {
            float bos = bo[0];
            int tg0 = t0 + mb + gid;
            int tg8 = tg0 + 8;
            if (tg0 < T_LEN)
                g_scores[b * TPAD + tg0] = mask[b * T_LEN + tg0] ? srow0 + bos : -1e9f;
            else if (tg0 < TPAD)
                g_scores[b * TPAD + tg0] = -1e9f;
            if (tg8 < T_LEN)
                g_scores[b * TPAD + tg8] = mask[b * T_LEN + tg8] ? srow8 + bos : -1e9f;
            else if (tg8 < TPAD)
                g_scores[b * TPAD + tg8] = -1e9f;
        }
    }
}

// ---------------------------------------------------------------------------
// Kernel B: softmax over 224 scores + interest vector (re-gather keys).
// ---------------------------------------------------------------------------
__global__ void __launch_bounds__(256, 8)
din_softmax_kernel(const int* __restrict__ hist,
                   const float* __restrict__ item_table)
{
    __shared__ float SC[TPAD];
    __shared__ float WG[TPAD];
    __shared__ float RED[8];
    __shared__ float SV[2];

    const int b    = blockIdx.x;
    const int tid  = threadIdx.x;
    const int lane = tid & 31;
    const int warp = tid >> 5;

    float s = (tid < TPAD) ? g_scores[b * TPAD + tid] : -3.4e38f;
    if (tid < TPAD) SC[tid] = s;

    float m = s;
    #pragma unroll
    for (int off = 16; off > 0; off >>= 1)
        m = fmaxf(m, __shfl_xor_sync(0xffffffffu, m, off));
    if (lane == 0) RED[warp] = m;
    __syncthreads();
    if (warp == 0) {
        float mm = (lane < 7) ? RED[lane] : -3.4e38f;
        #pragma unroll
        for (int off = 4; off > 0; off >>= 1)
            mm = fmaxf(mm, __shfl_xor_sync(0xffffffffu, mm, off));
        if (lane == 0) SV[0] = mm;
    }
    __syncthreads();

    float e = 0.f;
    if (tid < TPAD) {
        e = expf(SC[tid] - SV[0]);
        WG[tid] = e;
    }
    #pragma unroll
    for (int off = 16; off > 0; off >>= 1)
        e += __shfl_xor_sync(0xffffffffu, e, off);
    if (lane == 0) RED[warp] = e;
    __syncthreads();
    if (warp == 0) {
        float t2 = (lane < 7) ? RED[lane] : 0.f;
        #pragma unroll
        for (int off = 4; off > 0; off >>= 1)
            t2 += __shfl_xor_sync(0xffffffffu, t2, off);
        if (lane == 0) SV[1] = t2;
    }
    __syncthreads();

    const int e0 = warp * 8;
    float a0=0.f,a1=0.f,a2=0.f,a3=0.f,a4=0.f,a5=0.f,a6=0.f,a7=0.f;
    #pragma unroll
    for (int i = 0; i < 7; ++i) {
        int t = lane + 32 * i;
        float wv = WG[t];
        if (t < T_LEN) {
            int row = hist[b * T_LEN + t];
            const float* kp = item_table + (long)row * E_DIM + e0;
            float4 va = *(const float4*)(kp);
            float4 vb = *(const float4*)(kp + 4);
            a0 += wv * va.x; a1 += wv * va.y; a2 += wv * va.z; a3 += wv * va.w;
            a4 += wv * vb.x; a5 += wv * vb.y; a6 += wv * vb.z; a7 += wv * vb.w;
        }
    }
    #pragma unroll
    for (int off = 16; off > 0; off >>= 1) {
        a0 += __shfl_xor_sync(0xffffffffu, a0, off);
        a1 += __shfl_xor_sync(0xffffffffu, a1, off);
        a2 += __shfl_xor_sync(0xffffffffu, a2, off);
        a3 += __shfl_xor_sync(0xffffffffu, a3, off);
        a4 += __shfl_xor_sync(0xffffffffu, a4, off);
        a5 += __shfl_xor_sync(0xffffffffu, a5, off);
        a6 += __shfl_xor_sync(0xffffffffu, a6, off);
        a7 += __shfl_xor_sync(0xffffffffu, a7, off);
    }
    if (lane == 0) {
        float invs = 1.0f / SV[1];
        float* gi = g_interest + (long)b * E_DIM + e0;
        gi[0]=a0*invs; gi[1]=a1*invs; gi[2]=a2*invs; gi[3]=a3*invs;
        gi[4]=a4*invs; gi[5]=a5*invs; gi[6]=a6*invs; gi[7]=a7*invs;
    }
}

// ---------------------------------------------------------------------------
// Kernel C: final MLP, 8 rows/CTA, 512 threads, K-split partials.
// ---------------------------------------------------------------------------
#define BTILE 8
#define C_AT   0
#define C_P    2176
#define C_H1   (2176 + 5120)
#define C_Q    (2176 + 5120 + 3072)
#define C_R    (2176 + 5120 + 3072 + 5120)
#define SMEMC_BYTES ((2176 + 5120 + 3072 + 5120 + 32) * 4)

__global__ void __launch_bounds__(512, 2)
din_mlp_kernel(const int* __restrict__ tgt,
               const int* __restrict__ sf,
               const float* __restrict__ dense,
               const float* __restrict__ item_table,
               const float* __restrict__ user_table,
               const float* __restrict__ ctx_table,
               const float* __restrict__ w1, const float* __restrict__ b1,
               const float* __restrict__ w2, const float* __restrict__ b2,
               const float* __restrict__ ow, const float* __restrict__ ob,
               float* __restrict__ out)
{
    extern __shared__ float smc[];
    float* At  = smc + C_AT;
    float* P   = smc + C_P;
    float* H1t = smc + C_H1;
    float* Qp  = smc + C_Q;
    float* R   = smc + C_R;

    const int b0   = blockIdx.x * BTILE;
    const int tid  = threadIdx.x;
    const int lane = tid & 31;

    for (int i = tid; i < 272 * BTILE; i += 512) {
        int bb = i & (BTILE - 1);
        int k  = i / BTILE;
        int gb = b0 + bb;
        float v;
        if (k < 64)        v = user_table[(long)sf[gb * 2] * 64 + k];
        else if (k < 128)  v = ctx_table[(long)sf[gb * 2 + 1] * 64 + (k - 64)];
        else if (k < 192)  v = item_table[(long)tgt[gb] * 64 + (k - 128)];
        else if (k < 256)  v = g_interest[(long)gb * 64 + (k - 192)];
        else               v = dense[gb * 16 + (k - 256)];
        At[k * BTILE + bb] = v;
    }
    __syncthreads();

    {
        const int n  = tid & 255;
        const int ks = tid >> 8;
        const int k0 = ks * 136;
        float2 acc[4];
        #pragma unroll
        for (int p = 0; p < 4; ++p) acc[p] = make_float2(0.f, 0.f);
        #pragma unroll 4
        for (int k = k0; k < k0 + 136; ++k) {
            float wv = w1[k * 256 + n];
            float2 bb = make_float2(wv, wv);
            const float4* ar4 = (const float4*)(At + k * BTILE);
            float4 aA = ar4[0];
            float4 aB = ar4[1];
            acc[0] = fma2(make_float2(aA.x, aA.y), bb, acc[0]);
            acc[1] = fma2(make_float2(aA.z, aA.w), bb, acc[1]);
            acc[2] = fma2(make_float2(aB.x, aB.y), bb, acc[2]);
            acc[3] = fma2(make_float2(aB.z, aB.w), bb, acc[3]);
        }
        float* pr = P + tid * 10;
        #pragma unroll
        for (int p = 0; p < 4; ++p) *(float2*)(pr + 2 * p) = acc[p];
    }
    __syncthreads();

    if (tid < 256) {
        float bias = b1[tid];
        const float* p0 = P + tid * 10;
        const float* p1 = P + (tid + 256) * 10;
        #pragma unroll
        for (int p = 0; p < 4; ++p) {
            float2 x = *(const float2*)(p0 + 2 * p);
            float2 y = *(const float2*)(p1 + 2 * p);
            float2 r = make_float2(fmaxf(x.x + y.x + bias, 0.f),
                                   fmaxf(x.y + y.y + bias, 0.f));
            *(float2*)(H1t + tid * 12 + 2 * p) = r;
        }
    }
    __syncthreads();

    {
        const int n  = tid & 127;
        const int ks = tid >> 7;
        const int k0 = ks * 64;
        float2 acc[4];
        #pragma unroll
        for (int p = 0; p < 4; ++p) acc[p] = make_float2(0.f, 0.f);
        #pragma unroll 4
        for (int k = k0; k < k0 + 64; ++k) {
            float wv = w2[k * 128 + n];
            float2 bb = make_float2(wv, wv);
            const float4* hr4 = (const float4*)(H1t + k * 12);
            float4 aA = hr4[0];
            float4 aB = hr4[1];
            acc[0] = fma2(make_float2(aA.x, aA.y), bb, acc[0]);
            acc[1] = fma2(make_float2(aA.z, aA.w), bb, acc[1]);
            acc[2] = fma2(make_float2(aB.x, aB.y), bb, acc[2]);
            acc[3] = fma2(make_float2(aB.z, aB.w), bb, acc[3]);
        }
        float* qr = Qp + tid * 10;
        #pragma unroll
        for (int p = 0; p < 4; ++p) *(float2*)(qr + 2 * p) = acc[p];
    }
    __syncthreads();

    if (tid < 128) {
        const int n = tid;
        float bias = b2[n];
        float owl  = ow[n];
        float s[8];
        #pragma unroll
        for (int m = 0; m < 8; ++m) {
            float v = Qp[(n)       * 10 + m]
                    + Qp[(n + 128) * 10 + m]
                    + Qp[(n + 256) * 10 + m]
                    + Qp[(n + 384) * 10 + m];
            s[m] = fmaxf(v + bias, 0.f) * owl;
        }
        #pragma unroll
        for (int off = 16; off > 0; off >>= 1) {
            #pragma unroll
            for (int m = 0; m < 8; ++m)
                s[m] += __shfl_xor_sync(0xffffffffu, s[m], off);
        }
        if (lane == 0) {
            int w = tid >> 5;
            #pragma unroll
            for (int m = 0; m < 8; ++m) R[w * 8 + m] = s[m];
        }
    }
    __syncthreads();
    if (tid < BTILE) {
        float s = R[tid] + R[8 + tid] + R[16 + tid] + R[24 + tid] + ob[0];
        out[b0 + tid] = s;
    }
}

// ---------------------------------------------------------------------------
extern "C" void kernel_launch(void* const* d_in, const int* in_sizes, int n_in,
                              void* d_out, int out_size)
{
    const int*   tgt   = (const int*)d_in[0];
    const int*   hist  = (const int*)d_in[1];
    const int*   mask  = (const int*)d_in[2];
    const int*   sf    = (const int*)d_in[3];
    const float* dense = (const float*)d_in[4];
    const float* item_table = (const float*)d_in[5];
    const float* user_table = (const float*)d_in[6];
    const float* ctx_table  = (const float*)d_in[7];
    const float* att_w1 = (const float*)d_in[8];
    const float* att_b1 = (const float*)d_in[9];
    const float* att_w2 = (const float*)d_in[10];
    const float* att_b2 = (const float*)d_in[11];
    const float* att_wo = (const float*)d_in[12];
    const float* att_bo = (const float*)d_in[13];
    const float* mlp_w1 = (const float*)d_in[14];
    const float* mlp_b1 = (const float*)d_in[15];
    const float* mlp_w2 = (const float*)d_in[16];
    const float* mlp_b2 = (const float*)d_in[17];
    const float* out_w  = (const float*)d_in[18];
    const float* out_b  = (const float*)d_in[19];
    float*       out    = (float*)d_out;

    cudaFuncSetAttribute(din_scores_kernel, cudaFuncAttributeMaxDynamicSharedMemorySize, SMEMA_BYTES);
    cudaFuncSetAttribute(din_mlp_kernel,    cudaFuncAttributeMaxDynamicSharedMemorySize, SMEMC_BYTES);

    din_pack_kernel<<<(VOCAB_ITEM * 32 + 255) / 256, 256>>>(item_table, att_w2);

    din_fold_kernel<<<B_ROWS, 256>>>(tgt, item_table, att_w1, att_b1);

    din_scores_kernel<<<B_ROWS * 2, 256, SMEMA_BYTES>>>(
        tgt, hist, mask, att_b2, att_wo, att_bo);

    din_softmax_kernel<<<B_ROWS, 256>>>(hist, item_table);

    din_mlp_kernel<<<B_ROWS / BTILE, 512, SMEMC_BYTES>>>(
        tgt, sf, dense, item_table, user_table, ctx_table,
        mlp_w1, mlp_b1, mlp_w2, mlp_b2, out_w, out_b, out);
}

// round 12
// speedup vs baseline: 2.1254x; 1.1345x over previous
#include <cuda_runtime.h>
#include <cuda_bf16.h>
#include <cstdint>

// ---------------------------------------------------------------------------
// DIN forward.
//  Kernel P: pre-split item_table + w2 into packed bf16 hi/lo pairs
//  Kernel F: fold per-b attention weights -> packed g_w12H/L, g_qc
//  Kernel A: scores via mma.sync bf16 m16n8k16, 3-pass hi/lo; staging = copies
//  Kernel B: softmax + interest (coalesced row-major gather)
//  Kernel C: final MLP (fp32, k-split)
// ---------------------------------------------------------------------------

#define B_ROWS 4096
#define T_LEN  200
#define TPAD   224
#define E_DIM  64
#define VOCAB_ITEM 100000

__device__ uint32_t g_keyH[VOCAB_ITEM * 32];    // packed bf16-hi pairs per row
__device__ uint32_t g_keyL[VOCAB_ITEM * 32];    // packed bf16-lo pairs
__device__ uint32_t g_w12H[B_ROWS * 2048];      // [b][j][w] packed pairs
__device__ uint32_t g_w12L[B_ROWS * 2048];
__device__ uint32_t g_w2H[1024];                // [n][w]
__device__ uint32_t g_w2L[1024];
__device__ float g_qc[B_ROWS * 64];
__device__ float g_scores[B_ROWS * TPAD];
__device__ float g_interest[B_ROWS * E_DIM];

__device__ __forceinline__ float2 fma2(float2 a, float2 b, float2 c) {
    float2 d;
    asm("fma.rn.f32x2 %0, %1, %2, %3;"
        : "=l"(*(unsigned long long*)&d)
        : "l"(*(unsigned long long*)&a),
          "l"(*(unsigned long long*)&b),
          "l"(*(unsigned long long*)&c));
    return d;
}

// ---- bf16 split helpers ----
__device__ __forceinline__ void bsplit(float x, uint16_t& h, uint16_t& l) {
    __nv_bfloat16 bh = __float2bfloat16(x);
    float r = x - __bfloat162float(bh);
    __nv_bfloat16 bl = __float2bfloat16(r);
    h = *reinterpret_cast<uint16_t*>(&bh);
    l = *reinterpret_cast<uint16_t*>(&bl);
}
__device__ __forceinline__ uint32_t packu(uint16_t lo, uint16_t hi) {
    return (uint32_t)lo | ((uint32_t)hi << 16);
}
__device__ __forceinline__ void bsplit2(float e, float o, uint32_t& wh, uint32_t& wl) {
    uint16_t eh, el, oh, ol;
    bsplit(e, eh, el);
    bsplit(o, oh, ol);
    wh = packu(eh, oh);
    wl = packu(el, ol);
}

// D += A*B  (m16n8k16, A row-major, B col-major, bf16 in, f32 acc)
__device__ __forceinline__ void mmabf(float* d, const uint32_t* a, const uint32_t* b) {
    asm volatile(
        "mma.sync.aligned.m16n8k16.row.col.f32.bf16.bf16.f32 "
        "{%0,%1,%2,%3}, {%4,%5,%6,%7}, {%8,%9}, {%0,%1,%2,%3};"
        : "+f"(d[0]), "+f"(d[1]), "+f"(d[2]), "+f"(d[3])
        : "r"(a[0]), "r"(a[1]), "r"(a[2]), "r"(a[3]), "r"(b[0]), "r"(b[1]));
}

// ---------------------------------------------------------------------------
// Kernel P: pre-split item_table rows (and w2) into packed bf16 hi/lo pairs.
// ---------------------------------------------------------------------------
__global__ void __launch_bounds__(256)
din_pack_kernel(const float* __restrict__ item_table,
                const float* __restrict__ w2)
{
    long i = (long)blockIdx.x * 256 + threadIdx.x;   // pair index
    if (i < (long)VOCAB_ITEM * 32) {
        float2 v = ((const float2*)item_table)[i];
        uint32_t h, l;
        bsplit2(v.x, v.y, h, l);
        g_keyH[i] = h;
        g_keyL[i] = l;
    }
    if (i < 1024) {                                  // w2: n-major packed pairs
        int n = (int)i & 31, w = (int)i >> 5;
        float e = w2[(2 * w) * 32 + n];
        float o = w2[(2 * w + 1) * 32 + n];
        uint32_t h, l;
        bsplit2(e, o, h, l);
        g_w2H[n * 32 + w] = h;
        g_w2L[n * 32 + w] = l;
    }
}

// ---------------------------------------------------------------------------
// Kernel F: fold weights per b -> packed bf16 hi/lo, transposed [j][k-pairs].
// ---------------------------------------------------------------------------
__global__ void __launch_bounds__(256, 4)
din_fold_kernel(const int* __restrict__ tgt,
                const float* __restrict__ item_table,
                const float* __restrict__ w1, const float* __restrict__ b1)
{
    __shared__ float Q[64];
    __shared__ float SM[64 * 65];
    const int b   = blockIdx.x;
    const int tid = threadIdx.x;

    if (tid < 64) Q[tid] = item_table[(long)tgt[b] * 64 + tid];
    __syncthreads();

    for (int i = tid; i < 4096; i += 256) {
        int k = i >> 6, j = i & 63;
        SM[k * 65 + j] = w1[i] + w1[8192 + i] + Q[k] * w1[12288 + i];
    }
    __syncthreads();
    for (int i = tid; i < 2048; i += 256) {
        int j = i >> 5, w = i & 31;
        float e = SM[(2 * w) * 65 + j];
        float o = SM[(2 * w + 1) * 65 + j];
        uint32_t h, l;
        bsplit2(e, o, h, l);
        g_w12H[(long)b * 2048 + i] = h;
        g_w12L[(long)b * 2048 + i] = l;
    }
    if (tid < 64) {
        float s = b1[tid];
        #pragma unroll 8
        for (int e = 0; e < 64; ++e)
            s += Q[e] * (w1[4096 + e * 64 + tid] - w1[8192 + e * 64 + tid]);
        g_qc[b * 64 + tid] = s;
    }
}

// ---------------------------------------------------------------------------
// Kernel A: scores via mma.sync bf16 k16. grid = 2*B, 256 thr (8 warps x m16).
// Staging = pure uint4 copies from pre-split globals. smem 65KB -> 3 CTAs/SM.
// ---------------------------------------------------------------------------
#define SA_KH    0
#define SA_KL    4608
#define SA_W12H  9216
#define SA_W12L  11520
#define SA_W2H   13824
#define SA_W2L   14976
#define SA_QC    16128
#define SA_B2    16192
#define SA_WO    16224
#define SMEMA_WORDS 16256
#define SMEMA_BYTES (SMEMA_WORDS * 4)

__global__ void __launch_bounds__(256, 3)
din_scores_kernel(const int* __restrict__ tgt,
                  const int* __restrict__ hist,
                  const int* __restrict__ mask,
                  const float* __restrict__ b2,
                  const float* __restrict__ wo, const float* __restrict__ bo)
{
    extern __shared__ uint32_t smu[];
    uint32_t* KH   = smu + SA_KH;     // aliased by H1H after A-frag hoist
    uint32_t* KL   = smu + SA_KL;     // aliased by H1L
    uint32_t* W12H = smu + SA_W12H;
    uint32_t* W12L = smu + SA_W12L;
    uint32_t* W2H  = smu + SA_W2H;
    uint32_t* W2L  = smu + SA_W2L;
    float*    QC   = (float*)(smu + SA_QC);
    float*    B2S  = (float*)(smu + SA_B2);
    float*    WOS  = (float*)(smu + SA_WO);

    const int b    = blockIdx.x >> 1;
    const int t0   = (blockIdx.x & 1) * 128;
    const int tid  = threadIdx.x;
    const int lane = tid & 31;
    const int wid  = tid >> 5;      // 0..7
    const int gid  = lane >> 2;     // 0..7
    const int tig  = lane & 3;      // 0..3

    // ---- stage operands (pure copies) ----
    {
        const uint4* HV = (const uint4*)g_keyH;
        const uint4* LV = (const uint4*)g_keyL;
        for (int i = tid; i < 128 * 8; i += 256) {
            int f = i & 7, m = i >> 3;
            int tg = t0 + m;
            uint4 h = make_uint4(0u, 0u, 0u, 0u);
            uint4 l = make_uint4(0u, 0u, 0u, 0u);
            if (tg < T_LEN) {
                int row = hist[b * T_LEN + tg];
                h = HV[row * 8 + f];
                l = LV[row * 8 + f];
            }
            *(uint4*)(KH + m * 36 + 4 * f) = h;
            *(uint4*)(KL + m * 36 + 4 * f) = l;
        }
        const uint4* WH = (const uint4*)(g_w12H + (long)b * 2048);
        const uint4* WL = (const uint4*)(g_w12L + (long)b * 2048);
        for (int i = tid; i < 64 * 8; i += 256) {
            int f = i & 7, j = i >> 3;
            *(uint4*)(W12H + j * 36 + 4 * f) = WH[i];
            *(uint4*)(W12L + j * 36 + 4 * f) = WL[i];
        }
        const uint4* VH = (const uint4*)g_w2H;
        const uint4* VL = (const uint4*)g_w2L;
        if (tid < 256) {
            int i = tid;
            int f = i & 7, n = i >> 3;
            *(uint4*)(W2H + n * 36 + 4 * f) = VH[i];
            *(uint4*)(W2L + n * 36 + 4 * f) = VL[i];
        }
    }
    if (tid < 64) QC[tid] = g_qc[b * 64 + tid];
    if (tid < 32) { B2S[tid] = b2[tid]; WOS[tid] = wo[tid]; }
    __syncthreads();

    const int mb = wid * 16;

    // ---- GEMM1: H1[m][j] = relu(KEYS @ W12T^T + qc) ----
    {
        uint32_t ah[4][4], al[4][4];
        #pragma unroll
        for (int kc = 0; kc < 4; ++kc) {
            int a0 = (mb + gid) * 36 + kc * 8 + tig;
            int a1 = (mb + gid + 8) * 36 + kc * 8 + tig;
            ah[kc][0] = KH[a0]; ah[kc][1] = KH[a1];
            ah[kc][2] = KH[a0 + 4]; ah[kc][3] = KH[a1 + 4];
            al[kc][0] = KL[a0]; al[kc][1] = KL[a1];
            al[kc][2] = KL[a0 + 4]; al[kc][3] = KL[a1 + 4];
        }
        __syncthreads();   // KEYS dead; smem becomes H1

        #pragma unroll
        for (int nt = 0; nt < 8; ++nt) {
            float acc[4] = {0.f, 0.f, 0.f, 0.f};
            #pragma unroll
            for (int kc = 0; kc < 4; ++kc) {
                const int boff = (nt * 8 + gid) * 36 + kc * 8 + tig;
                uint32_t bh[2], bl[2];
                bh[0] = W12H[boff]; bh[1] = W12H[boff + 4];
                bl[0] = W12L[boff]; bl[1] = W12L[boff + 4];
                mmabf(acc, ah[kc], bh);
                mmabf(acc, ah[kc], bl);
                mmabf(acc, al[kc], bh);
            }
            int j0 = nt * 8 + 2 * tig;
            float q0 = QC[j0], q1 = QC[j0 + 1];
            float v0 = fmaxf(acc[0] + q0, 0.f);
            float v1 = fmaxf(acc[1] + q1, 0.f);
            float v2 = fmaxf(acc[2] + q0, 0.f);
            float v3 = fmaxf(acc[3] + q1, 0.f);
            uint32_t h01, l01, h23, l23;
            bsplit2(v0, v1, h01, l01);
            bsplit2(v2, v3, h23, l23);
            KH[(mb + gid) * 36 + nt * 4 + tig]     = h01;  // H1H
            KL[(mb + gid) * 36 + nt * 4 + tig]     = l01;  // H1L
            KH[(mb + gid + 8) * 36 + nt * 4 + tig] = h23;
            KL[(mb + gid + 8) * 36 + nt * 4 + tig] = l23;
        }
    }
    __syncwarp();   // H1 rows are warp-private

    // ---- GEMM2: scores = reduce_n relu(H1 @ W2T^T + b2)*wo ----
    {
        uint32_t ah[4][4], al[4][4];
        #pragma unroll
        for (int kc = 0; kc < 4; ++kc) {
            int a0 = (mb + gid) * 36 + kc * 8 + tig;
            int a1 = (mb + gid + 8) * 36 + kc * 8 + tig;
            ah[kc][0] = KH[a0]; ah[kc][1] = KH[a1];
            ah[kc][2] = KH[a0 + 4]; ah[kc][3] = KH[a1 + 4];
            al[kc][0] = KL[a0]; al[kc][1] = KL[a1];
            al[kc][2] = KL[a0 + 4]; al[kc][3] = KL[a1 + 4];
        }
        float srow0 = 0.f, srow8 = 0.f;
        #pragma unroll
        for (int nt = 0; nt < 4; ++nt) {
            float acc[4] = {0.f, 0.f, 0.f, 0.f};
            #pragma unroll
            for (int kc = 0; kc < 4; ++kc) {
                const int boff = (nt * 8 + gid) * 36 + kc * 8 + tig;
                uint32_t bh[2], bl[2];
                bh[0] = W2H[boff]; bh[1] = W2H[boff + 4];
                bl[0] = W2L[boff]; bl[1] = W2L[boff + 4];
                mmabf(acc, ah[kc], bh);
                mmabf(acc, ah[kc], bl);
                mmabf(acc, al[kc], bh);
            }
            int n0 = nt * 8 + 2 * tig;
            float bb0 = B2S[n0], bb1 = B2S[n0 + 1];
            float w0 = WOS[n0],  w1v = WOS[n0 + 1];
            srow0 += fmaxf(acc[0] + bb0, 0.f) * w0 + fmaxf(acc[1] + bb1, 0.f) * w1v;
            srow8 += fmaxf(acc[2] + bb0, 0.f) * w0 + fmaxf(acc[3] + bb1, 0.f) * w1v;
        }
        srow0 += __shfl_xor_sync(0xffffffffu, srow0, 1);
        srow0 += __shfl_xor_sync(0xffffffffu, srow0, 2);
        srow8 += __shfl_xor_sync(0xffffffffu, srow8, 1);
        srow8 += __shfl_xor_sync(0xffffffffu, srow8, 2);

        if (tig == 0) {
            float bos = bo[0];
            int tg0 = t0 + mb + gid;
            int tg8 = tg0 + 8;
            if (tg0 < T_LEN)
                g_scores[b * TPAD + tg0] = mask[b * T_LEN + tg0] ? srow0 + bos : -1e9f;
            else if (tg0 < TPAD)
                g_scores[b * TPAD + tg0] = -1e9f;
            if (tg8 < T_LEN)
                g_scores[b * TPAD + tg8] = mask[b * T_LEN + tg8] ? srow8 + bos : -1e9f;
            else if (tg8 < TPAD)
                g_scores[b * TPAD + tg8] = -1e9f;
        }
    }
}

// ---------------------------------------------------------------------------
// Kernel B: softmax over 224 scores + interest (coalesced gather).
// Warp w owns t = {w, w+8, ...} (25 each); lane owns e-pair (2*lane, 2*lane+1).
// Each t reads one contiguous 256B key row -> 2 wavefronts per load.
// ---------------------------------------------------------------------------
__global__ void __launch_bounds__(256, 8)
din_softmax_kernel(const int* __restrict__ hist,
                   const float* __restrict__ item_table)
{
    __shared__ float SC[TPAD];
    __shared__ float WG[TPAD];
    __shared__ float RED[8];
    __shared__ float SV[2];
    __shared__ float ACC[8 * 64];

    const int b    = blockIdx.x;
    const int tid  = threadIdx.x;
    const int lane = tid & 31;
    const int warp = tid >> 5;

    float s = (tid < TPAD) ? g_scores[b * TPAD + tid] : -3.4e38f;
    if (tid < TPAD) SC[tid] = s;

    float m = s;
    #pragma unroll
    for (int off = 16; off > 0; off >>= 1)
        m = fmaxf(m, __shfl_xor_sync(0xffffffffu, m, off));
    if (lane == 0) RED[warp] = m;
    __syncthreads();
    if (warp == 0) {
        float mm = (lane < 7) ? RED[lane] : -3.4e38f;
        #pragma unroll
        for (int off = 4; off > 0; off >>= 1)
            mm = fmaxf(mm, __shfl_xor_sync(0xffffffffu, mm, off));
        if (lane == 0) SV[0] = mm;
    }
    __syncthreads();

    float e = 0.f;
    if (tid < TPAD) {
        e = expf(SC[tid] - SV[0]);
        WG[tid] = e;
    }
    #pragma unroll
    for (int off = 16; off > 0; off >>= 1)
        e += __shfl_xor_sync(0xffffffffu, e, off);
    if (lane == 0) RED[warp] = e;
    __syncthreads();
    if (warp == 0) {
        float t2 = (lane < 7) ? RED[lane] : 0.f;
        #pragma unroll
        for (int off = 4; off > 0; off >>= 1)
            t2 += __shfl_xor_sync(0xffffffffu, t2, off);
        if (lane == 0) SV[1] = t2;
    }
    __syncthreads();

    // interest partials: warp-strided t, coalesced full-row reads
    {
        float a0 = 0.f, a1 = 0.f;
        #pragma unroll 5
        for (int i = 0; i < 25; ++i) {
            int t = warp + 8 * i;           // 8*25 = 200 exactly
            float wv = WG[t];
            int row = hist[b * T_LEN + t];
            float2 v = *(const float2*)(item_table + (long)row * E_DIM + 2 * lane);
            a0 += wv * v.x;
            a1 += wv * v.y;
        }
        *(float2*)(ACC + warp * 64 + 2 * lane) = make_float2(a0, a1);
    }
    __syncthreads();
    if (tid < 64) {
        float v = ACC[tid] + ACC[64 + tid] + ACC[128 + tid] + ACC[192 + tid]
                + ACC[256 + tid] + ACC[320 + tid] + ACC[384 + tid] + ACC[448 + tid];
        g_interest[(long)b * E_DIM + tid] = v / SV[1];
    }
}

// ---------------------------------------------------------------------------
// Kernel C: final MLP, 8 rows/CTA, 512 threads, K-split partials.
// ---------------------------------------------------------------------------
#define BTILE 8
#define C_AT   0
#define C_P    2176
#define C_H1   (2176 + 5120)
#define C_Q    (2176 + 5120 + 3072)
#define C_R    (2176 + 5120 + 3072 + 5120)
#define SMEMC_BYTES ((2176 + 5120 + 3072 + 5120 + 32) * 4)

__global__ void __launch_bounds__(512, 2)
din_mlp_kernel(const int* __restrict__ tgt,
               const int* __restrict__ sf,
               const float* __restrict__ dense,
               const float* __restrict__ item_table,
               const float* __restrict__ user_table,
               const float* __restrict__ ctx_table,
               const float* __restrict__ w1, const float* __restrict__ b1,
               const float* __restrict__ w2, const float* __restrict__ b2,
               const float* __restrict__ ow, const float* __restrict__ ob,
               float* __restrict__ out)
{
    extern __shared__ float smc[];
    float* At  = smc + C_AT;
    float* P   = smc + C_P;
    float* H1t = smc + C_H1;
    float* Qp  = smc + C_Q;
    float* R   = smc + C_R;

    const int b0   = blockIdx.x * BTILE;
    const int tid  = threadIdx.x;
    const int lane = tid & 31;

    for (int i = tid; i < 272 * BTILE; i += 512) {
        int bb = i & (BTILE - 1);
        int k  = i / BTILE;
        int gb = b0 + bb;
        float v;
        if (k < 64)        v = user_table[(long)sf[gb * 2] * 64 + k];
        else if (k < 128)  v = ctx_table[(long)sf[gb * 2 + 1] * 64 + (k - 64)];
        else if (k < 192)  v = item_table[(long)tgt[gb] * 64 + (k - 128)];
        else if (k < 256)  v = g_interest[(long)gb * 64 + (k - 192)];
        else               v = dense[gb * 16 + (k - 256)];
        At[k * BTILE + bb] = v;
    }
    __syncthreads();

    {
        const int n  = tid & 255;
        const int ks = tid >> 8;
        const int k0 = ks * 136;
        float2 acc[4];
        #pragma unroll
        for (int p = 0; p < 4; ++p) acc[p] = make_float2(0.f, 0.f);
        #pragma unroll 4
        for (int k = k0; k < k0 + 136; ++k) {
            float wv = w1[k * 256 + n];
            float2 bb = make_float2(wv, wv);
            const float4* ar4 = (const float4*)(At + k * BTILE);
            float4 aA = ar4[0];
            float4 aB = ar4[1];
            acc[0] = fma2(make_float2(aA.x, aA.y), bb, acc[0]);
            acc[1] = fma2(make_float2(aA.z, aA.w), bb, acc[1]);
            acc[2] = fma2(make_float2(aB.x, aB.y), bb, acc[2]);
            acc[3] = fma2(make_float2(aB.z, aB.w), bb, acc[3]);
        }
        float* pr = P + tid * 10;
        #pragma unroll
        for (int p = 0; p < 4; ++p) *(float2*)(pr + 2 * p) = acc[p];
    }
    __syncthreads();

    if (tid < 256) {
        float bias = b1[tid];
        const float* p0 = P + tid * 10;
        const float* p1 = P + (tid + 256) * 10;
        #pragma unroll
        for (int p = 0; p < 4; ++p) {
            float2 x = *(const float2*)(p0 + 2 * p);
            float2 y = *(const float2*)(p1 + 2 * p);
            float2 r = make_float2(fmaxf(x.x + y.x + bias, 0.f),
                                   fmaxf(x.y + y.y + bias, 0.f));
            *(float2*)(H1t + tid * 12 + 2 * p) = r;
        }
    }
    __syncthreads();

    {
        const int n  = tid & 127;
        const int ks = tid >> 7;
        const int k0 = ks * 64;
        float2 acc[4];
        #pragma unroll
        for (int p = 0; p < 4; ++p) acc[p] = make_float2(0.f, 0.f);
        #pragma unroll 4
        for (int k = k0; k < k0 + 64; ++k) {
            float wv = w2[k * 128 + n];
            float2 bb = make_float2(wv, wv);
            const float4* hr4 = (const float4*)(H1t + k * 12);
            float4 aA = hr4[0];
            float4 aB = hr4[1];
            acc[0] = fma2(make_float2(aA.x, aA.y), bb, acc[0]);
            acc[1] = fma2(make_float2(aA.z, aA.w), bb, acc[1]);
            acc[2] = fma2(make_float2(aB.x, aB.y), bb, acc[2]);
            acc[3] = fma2(make_float2(aB.z, aB.w), bb, acc[3]);
        }
        float* qr = Qp + tid * 10;
        #pragma unroll
        for (int p = 0; p < 4; ++p) *(float2*)(qr + 2 * p) = acc[p];
    }
    __syncthreads();

    if (tid < 128) {
        const int n = tid;
        float bias = b2[n];
        float owl  = ow[n];
        float s[8];
        #pragma unroll
        for (int m = 0; m < 8; ++m) {
            float v = Qp[(n)       * 10 + m]
                    + Qp[(n + 128) * 10 + m]
                    + Qp[(n + 256) * 10 + m]
                    + Qp[(n + 384) * 10 + m];
            s[m] = fmaxf(v + bias, 0.f) * owl;
        }
        #pragma unroll
        for (int off = 16; off > 0; off >>= 1) {
            #pragma unroll
            for (int m = 0; m < 8; ++m)
                s[m] += __shfl_xor_sync(0xffffffffu, s[m], off);
        }
        if (lane == 0) {
            int w = tid >> 5;
            #pragma unroll
            for (int m = 0; m < 8; ++m) R[w * 8 + m] = s[m];
        }
    }
    __syncthreads();
    if (tid < BTILE) {
        float s = R[tid] + R[8 + tid] + R[16 + tid] + R[24 + tid] + ob[0];
        out[b0 + tid] = s;
    }
}

// ---------------------------------------------------------------------------
extern "C" void kernel_launch(void* const* d_in, const int* in_sizes, int n_in,
                              void* d_out, int out_size)
{
    const int*   tgt   = (const int*)d_in[0];
    const int*   hist  = (const int*)d_in[1];
    const int*   mask  = (const int*)d_in[2];
    const int*   sf    = (const int*)d_in[3];
    const float* dense = (const float*)d_in[4];
    const float* item_table = (const float*)d_in[5];
    const float* user_table = (const float*)d_in[6];
    const float* ctx_table  = (const float*)d_in[7];
    const float* att_w1 = (const float*)d_in[8];
    const float* att_b1 = (const float*)d_in[9];
    const float* att_w2 = (const float*)d_in[10];
    const float* att_b2 = (const float*)d_in[11];
    const float* att_wo = (const float*)d_in[12];
    const float* att_bo = (const float*)d_in[13];
    const float* mlp_w1 = (const float*)d_in[14];
    const float* mlp_b1 = (const float*)d_in[15];
    const float* mlp_w2 = (const float*)d_in[16];
    const float* mlp_b2 = (const float*)d_in[17];
    const float* out_w  = (const float*)d_in[18];
    const float* out_b  = (const float*)d_in[19];
    float*       out    = (float*)d_out;

    cudaFuncSetAttribute(din_scores_kernel, cudaFuncAttributeMaxDynamicSharedMemorySize, SMEMA_BYTES);
    cudaFuncSetAttribute(din_mlp_kernel,    cudaFuncAttributeMaxDynamicSharedMemorySize, SMEMC_BYTES);

    din_pack_kernel<<<(VOCAB_ITEM * 32 + 255) / 256, 256>>>(item_table, att_w2);

    din_fold_kernel<<<B_ROWS, 256>>>(tgt, item_table, att_w1, att_b1);

    din_scores_kernel<<<B_ROWS * 2, 256, SMEMA_BYTES>>>(
        tgt, hist, mask, att_b2, att_wo, att_bo);

    din_softmax_kernel<<<B_ROWS, 256>>>(hist, item_table);

    din_mlp_kernel<<<B_ROWS / BTILE, 512, SMEMC_BYTES>>>(
        tgt, sf, dense, item_table, user_table, ctx_table,
        mlp_w1, mlp_b1, mlp_w2, mlp_b2, out_w, out_b, out);
}

// round 14
// speedup vs baseline: 2.2970x; 1.0807x over previous
#include <cuda_runtime.h>
#include <cuda_bf16.h>
#include <cstdint>

// ---------------------------------------------------------------------------
// DIN forward.
//  Kernel P: pre-split item_table + w2 + mlp weights into packed bf16 hi/lo
//  Kernel F: fold per-b attention weights -> packed g_w12H/L, g_qc
//  Kernel A: scores via mma.sync bf16 m16n8k16, 3-pass hi/lo; staging = copies
//  Kernel B: softmax + interest (coalesced row-major gather)
//  Kernel C: final MLP via bf16 MMA (B frags direct from global)
// ---------------------------------------------------------------------------

#define B_ROWS 4096
#define T_LEN  200
#define TPAD   224
#define E_DIM  64
#define VOCAB_ITEM 100000

__device__ uint32_t g_keyH[VOCAB_ITEM * 32];    // packed bf16-hi pairs per row
__device__ uint32_t g_keyL[VOCAB_ITEM * 32];    // packed bf16-lo pairs
__device__ uint32_t g_w12H[B_ROWS * 2048];      // [b][j][w] packed pairs
__device__ uint32_t g_w12L[B_ROWS * 2048];
__device__ uint32_t g_w2H[1024];                // [n][w]
__device__ uint32_t g_w2L[1024];
__device__ uint32_t g_m1H[256 * 136];           // mlp_w1 [n][w] packed pairs
__device__ uint32_t g_m1L[256 * 136];
__device__ uint32_t g_m2H[128 * 128];           // mlp_w2 [n][w]
__device__ uint32_t g_m2L[128 * 128];
__device__ float g_qc[B_ROWS * 64];
__device__ float g_scores[B_ROWS * TPAD];
__device__ float g_interest[B_ROWS * E_DIM];

// ---- bf16 split helpers ----
__device__ __forceinline__ void bsplit(float x, uint16_t& h, uint16_t& l) {
    __nv_bfloat16 bh = __float2bfloat16(x);
    float r = x - __bfloat162float(bh);
    __nv_bfloat16 bl = __float2bfloat16(r);
    h = *reinterpret_cast<uint16_t*>(&bh);
    l = *reinterpret_cast<uint16_t*>(&bl);
}
__device__ __forceinline__ uint32_t packu(uint16_t lo, uint16_t hi) {
    return (uint32_t)lo | ((uint32_t)hi << 16);
}
__device__ __forceinline__ void bsplit2(float e, float o, uint32_t& wh, uint32_t& wl) {
    uint16_t eh, el, oh, ol;
    bsplit(e, eh, el);
    bsplit(o, oh, ol);
    wh = packu(eh, oh);
    wl = packu(el, ol);
}

// D += A*B  (m16n8k16, A row-major, B col-major, bf16 in, f32 acc)
__device__ __forceinline__ void mmabf(float* d, const uint32_t* a, const uint32_t* b) {
    asm volatile(
        "mma.sync.aligned.m16n8k16.row.col.f32.bf16.bf16.f32 "
        "{%0,%1,%2,%3}, {%4,%5,%6,%7}, {%8,%9}, {%0,%1,%2,%3};"
        : "+f"(d[0]), "+f"(d[1]), "+f"(d[2]), "+f"(d[3])
        : "r"(a[0]), "r"(a[1]), "r"(a[2]), "r"(a[3]), "r"(b[0]), "r"(b[1]));
}

// ---------------------------------------------------------------------------
// Kernel P: pre-split item_table / w2 / mlp weights into packed bf16 hi/lo.
// ---------------------------------------------------------------------------
__global__ void __launch_bounds__(256)
din_pack_kernel(const float* __restrict__ item_table,
                const float* __restrict__ w2,
                const float* __restrict__ m1,   // mlp_w1 [272][256]
                const float* __restrict__ m2)   // mlp_w2 [256][128]
{
    long i = (long)blockIdx.x * 256 + threadIdx.x;   // pair index
    if (i < (long)VOCAB_ITEM * 32) {
        float2 v = ((const float2*)item_table)[i];
        uint32_t h, l;
        bsplit2(v.x, v.y, h, l);
        g_keyH[i] = h;
        g_keyL[i] = l;
    }
    if (i < 1024) {                                  // att w2: n-major pairs
        int n = (int)i & 31, w = (int)i >> 5;
        float e = w2[(2 * w) * 32 + n];
        float o = w2[(2 * w + 1) * 32 + n];
        uint32_t h, l;
        bsplit2(e, o, h, l);
        g_w2H[n * 32 + w] = h;
        g_w2L[n * 32 + w] = l;
    }
    if (i < 256 * 136) {                             // mlp_w1 [n][w]
        int n = (int)(i / 136), w = (int)(i % 136);
        float e = m1[(2 * w) * 256 + n];
        float o = m1[(2 * w + 1) * 256 + n];
        uint32_t h, l;
        bsplit2(e, o, h, l);
        g_m1H[i] = h;
        g_m1L[i] = l;
    }
    if (i < 128 * 128) {                             // mlp_w2 [n][w]
        int n = (int)(i >> 7), w = (int)(i & 127);
        float e = m2[(2 * w) * 128 + n];
        float o = m2[(2 * w + 1) * 128 + n];
        uint32_t h, l;
        bsplit2(e, o, h, l);
        g_m2H[i] = h;
        g_m2L[i] = l;
    }
}

// ---------------------------------------------------------------------------
// Kernel F: fold weights per b -> packed bf16 hi/lo, transposed [j][k-pairs].
// ---------------------------------------------------------------------------
__global__ void __launch_bounds__(256, 4)
din_fold_kernel(const int* __restrict__ tgt,
                const float* __restrict__ item_table,
                const float* __restrict__ w1, const float* __restrict__ b1)
{
    __shared__ float Q[64];
    __shared__ float SM[64 * 65];
    const int b   = blockIdx.x;
    const int tid = threadIdx.x;

    if (tid < 64) Q[tid] = item_table[(long)tgt[b] * 64 + tid];
    __syncthreads();

    for (int i = tid; i < 4096; i += 256) {
        int k = i >> 6, j = i & 63;
        SM[k * 65 + j] = w1[i] + w1[8192 + i] + Q[k] * w1[12288 + i];
    }
    __syncthreads();
    for (int i = tid; i < 2048; i += 256) {
        int j = i >> 5, w = i & 31;
        float e = SM[(2 * w) * 65 + j];
        float o = SM[(2 * w + 1) * 65 + j];
        uint32_t h, l;
        bsplit2(e, o, h, l);
        g_w12H[(long)b * 2048 + i] = h;
        g_w12L[(long)b * 2048 + i] = l;
    }
    if (tid < 64) {
        float s = b1[tid];
        #pragma unroll 8
        for (int e = 0; e < 64; ++e)
            s += Q[e] * (w1[4096 + e * 64 + tid] - w1[8192 + e * 64 + tid]);
        g_qc[b * 64 + tid] = s;
    }
}

// ---------------------------------------------------------------------------
// Kernel A: scores via mma.sync bf16 k16. grid = 2*B, 256 thr (8 warps x m16).
// Staging = pure uint4 copies from pre-split globals. smem 65KB -> 3 CTAs/SM.
// ---------------------------------------------------------------------------
#define SA_KH    0
#define SA_KL    4608
#define SA_W12H  9216
#define SA_W12L  11520
#define SA_W2H   13824
#define SA_W2L   14976
#define SA_QC    16128
#define SA_B2    16192
#define SA_WO    16224
#define SMEMA_WORDS 16256
#define SMEMA_BYTES (SMEMA_WORDS * 4)

__global__ void __launch_bounds__(256, 3)
din_scores_kernel(const int* __restrict__ tgt,
                  const int* __restrict__ hist,
                  const int* __restrict__ mask,
                  const float* __restrict__ b2,
                  const float* __restrict__ wo, const float* __restrict__ bo)
{
    extern __shared__ uint32_t smu[];
    uint32_t* KH   = smu + SA_KH;     // aliased by H1H after A-frag hoist
    uint32_t* KL   = smu + SA_KL;     // aliased by H1L
    uint32_t* W12H = smu + SA_W12H;
    uint32_t* W12L = smu + SA_W12L;
    uint32_t* W2H  = smu + SA_W2H;
    uint32_t* W2L  = smu + SA_W2L;
    float*    QC   = (float*)(smu + SA_QC);
    float*    B2S  = (float*)(smu + SA_B2);
    float*    WOS  = (float*)(smu + SA_WO);

    const int b    = blockIdx.x >> 1;
    const int t0   = (blockIdx.x & 1) * 128;
    const int tid  = threadIdx.x;
    const int lane = tid & 31;
    const int wid  = tid >> 5;      // 0..7
    const int gid  = lane >> 2;     // 0..7
    const int tig  = lane & 3;      // 0..3

    // ---- stage operands (pure copies) ----
    {
        const uint4* HV = (const uint4*)g_keyH;
        const uint4* LV = (const uint4*)g_keyL;
        for (int i = tid; i < 128 * 8; i += 256) {
            int f = i & 7, m = i >> 3;
            int tg = t0 + m;
            uint4 h = make_uint4(0u, 0u, 0u, 0u);
            uint4 l = make_uint4(0u, 0u, 0u, 0u);
            if (tg < T_LEN) {
                int row = hist[b * T_LEN + tg];
                h = HV[row * 8 + f];
                l = LV[row * 8 + f];
            }
            *(uint4*)(KH + m * 36 + 4 * f) = h;
            *(uint4*)(KL + m * 36 + 4 * f) = l;
        }
        const uint4* WH = (const uint4*)(g_w12H + (long)b * 2048);
        const uint4* WL = (const uint4*)(g_w12L + (long)b * 2048);
        for (int i = tid; i < 64 * 8; i += 256) {
            int f = i & 7, j = i >> 3;
            *(uint4*)(W12H + j * 36 + 4 * f) = WH[i];
            *(uint4*)(W12L + j * 36 + 4 * f) = WL[i];
        }
        const uint4* VH = (const uint4*)g_w2H;
        const uint4* VL = (const uint4*)g_w2L;
        if (tid < 256) {
            int i = tid;
            int f = i & 7, n = i >> 3;
            *(uint4*)(W2H + n * 36 + 4 * f) = VH[i];
            *(uint4*)(W2L + n * 36 + 4 * f) = VL[i];
        }
    }
    if (tid < 64) QC[tid] = g_qc[b * 64 + tid];
    if (tid < 32) { B2S[tid] = b2[tid]; WOS[tid] = wo[tid]; }
    __syncthreads();

    const int mb = wid * 16;

    // ---- GEMM1: H1[m][j] = relu(KEYS @ W12T^T + qc) ----
    {
        uint32_t ah[4][4], al[4][4];
        #pragma unroll
        for (int kc = 0; kc < 4; ++kc) {
            int a0 = (mb + gid) * 36 + kc * 8 + tig;
            int a1 = (mb + gid + 8) * 36 + kc * 8 + tig;
            ah[kc][0] = KH[a0]; ah[kc][1] = KH[a1];
            ah[kc][2] = KH[a0 + 4]; ah[kc][3] = KH[a1 + 4];
            al[kc][0] = KL[a0]; al[kc][1] = KL[a1];
            al[kc][2] = KL[a0 + 4]; al[kc][3] = KL[a1 + 4];
        }
        __syncthreads();   // KEYS dead; smem becomes H1

        #pragma unroll
        for (int nt = 0; nt < 8; ++nt) {
            float acc[4] = {0.f, 0.f, 0.f, 0.f};
            #pragma unroll
            for (int kc = 0; kc < 4; ++kc) {
                const int boff = (nt * 8 + gid) * 36 + kc * 8 + tig;
                uint32_t bh[2], bl[2];
                bh[0] = W12H[boff]; bh[1] = W12H[boff + 4];
                bl[0] = W12L[boff]; bl[1] = W12L[boff + 4];
                mmabf(acc, ah[kc], bh);
                mmabf(acc, ah[kc], bl);
                mmabf(acc, al[kc], bh);
            }
            int j0 = nt * 8 + 2 * tig;
            float q0 = QC[j0], q1 = QC[j0 + 1];
            float v0 = fmaxf(acc[0] + q0, 0.f);
            float v1 = fmaxf(acc[1] + q1, 0.f);
            float v2 = fmaxf(acc[2] + q0, 0.f);
            float v3 = fmaxf(acc[3] + q1, 0.f);
            uint32_t h01, l01, h23, l23;
            bsplit2(v0, v1, h01, l01);
            bsplit2(v2, v3, h23, l23);
            KH[(mb + gid) * 36 + nt * 4 + tig]     = h01;  // H1H
            KL[(mb + gid) * 36 + nt * 4 + tig]     = l01;  // H1L
            KH[(mb + gid + 8) * 36 + nt * 4 + tig] = h23;
            KL[(mb + gid + 8) * 36 + nt * 4 + tig] = l23;
        }
    }
    __syncwarp();   // H1 rows are warp-private

    // ---- GEMM2: scores = reduce_n relu(H1 @ W2T^T + b2)*wo ----
    {
        uint32_t ah[4][4], al[4][4];
        #pragma unroll
        for (int kc = 0; kc < 4; ++kc) {
            int a0 = (mb + gid) * 36 + kc * 8 + tig;
            int a1 = (mb + gid + 8) * 36 + kc * 8 + tig;
            ah[kc][0] = KH[a0]; ah[kc][1] = KH[a1];
            ah[kc][2] = KH[a0 + 4]; ah[kc][3] = KH[a1 + 4];
            al[kc][0] = KL[a0]; al[kc][1] = KL[a1];
            al[kc][2] = KL[a0 + 4]; al[kc][3] = KL[a1 + 4];
        }
        float srow0 = 0.f, srow8 = 0.f;
        #pragma unroll
        for (int nt = 0; nt < 4; ++nt) {
            float acc[4] = {0.f, 0.f, 0.f, 0.f};
            #pragma unroll
            for (int kc = 0; kc < 4; ++kc) {
                const int boff = (nt * 8 + gid) * 36 + kc * 8 + tig;
                uint32_t bh[2], bl[2];
                bh[0] = W2H[boff]; bh[1] = W2H[boff + 4];
                bl[0] = W2L[boff]; bl[1] = W2L[boff + 4];
                mmabf(acc, ah[kc], bh);
                mmabf(acc, ah[kc], bl);
                mmabf(acc, al[kc], bh);
            }
            int n0 = nt * 8 + 2 * tig;
            float bb0 = B2S[n0], bb1 = B2S[n0 + 1];
            float w0 = WOS[n0],  w1v = WOS[n0 + 1];
            srow0 += fmaxf(acc[0] + bb0, 0.f) * w0 + fmaxf(acc[1] + bb1, 0.f) * w1v;
            srow8 += fmaxf(acc[2] + bb0, 0.f) * w0 + fmaxf(acc[3] + bb1, 0.f) * w1v;
        }
        srow0 += __shfl_xor_sync(0xffffffffu, srow0, 1);
        srow0 += __shfl_xor_sync(0xffffffffu, srow0, 2);
        srow8 += __shfl_xor_sync(0xffffffffu, srow8, 1);
        srow8 += __shfl_xor_sync(0xffffffffu, srow8, 2);

        if (tig == 0) {
            float bos = bo[0];
            int tg0 = t0 + mb + gid;
            int tg8 = tg0 + 8;
            if (tg0 < T_LEN)
                g_scores[b * TPAD + tg0] = mask[b * T_LEN + tg0] ? srow0 + bos : -1e9f;
            else if (tg0 < TPAD)
                g_scores[b * TPAD + tg0] = -1e9f;
            if (tg8 < T_LEN)
                g_scores[b * TPAD + tg8] = mask[b * T_LEN + tg8] ? srow8 + bos : -1e9f;
            else if (tg8 < TPAD)
                g_scores[b * TPAD + tg8] = -1e9f;
        }
    }
}

// ---------------------------------------------------------------------------
// Kernel B: softmax over 224 scores + interest (coalesced gather).
// ---------------------------------------------------------------------------
__global__ void __launch_bounds__(256, 8)
din_softmax_kernel(const int* __restrict__ hist,
                   const float* __restrict__ item_table)
{
    __shared__ float SC[TPAD];
    __shared__ float WG[TPAD];
    __shared__ float RED[8];
    __shared__ float SV[2];
    __shared__ float ACC[8 * 64];

    const int b    = blockIdx.x;
    const int tid  = threadIdx.x;
    const int lane = tid & 31;
    const int warp = tid >> 5;

    float s = (tid < TPAD) ? g_scores[b * TPAD + tid] : -3.4e38f;
    if (tid < TPAD) SC[tid] = s;

    float m = s;
    #pragma unroll
    for (int off = 16; off > 0; off >>= 1)
        m = fmaxf(m, __shfl_xor_sync(0xffffffffu, m, off));
    if (lane == 0) RED[warp] = m;
    __syncthreads();
    if (warp == 0) {
        float mm = (lane < 7) ? RED[lane] : -3.4e38f;
        #pragma unroll
        for (int off = 4; off > 0; off >>= 1)
            mm = fmaxf(mm, __shfl_xor_sync(0xffffffffu, mm, off));
        if (lane == 0) SV[0] = mm;
    }
    __syncthreads();

    float e = 0.f;
    if (tid < TPAD) {
        e = expf(SC[tid] - SV[0]);
        WG[tid] = e;
    }
    #pragma unroll
    for (int off = 16; off > 0; off >>= 1)
        e += __shfl_xor_sync(0xffffffffu, e, off);
    if (lane == 0) RED[warp] = e;
    __syncthreads();
    if (warp == 0) {
        float t2 = (lane < 7) ? RED[lane] : 0.f;
        #pragma unroll
        for (int off = 4; off > 0; off >>= 1)
            t2 += __shfl_xor_sync(0xffffffffu, t2, off);
        if (lane == 0) SV[1] = t2;
    }
    __syncthreads();

    {
        float a0 = 0.f, a1 = 0.f;
        #pragma unroll 5
        for (int i = 0; i < 25; ++i) {
            int t = warp + 8 * i;           // 8*25 = 200 exactly
            float wv = WG[t];
            int row = hist[b * T_LEN + t];
            float2 v = *(const float2*)(item_table + (long)row * E_DIM + 2 * lane);
            a0 += wv * v.x;
            a1 += wv * v.y;
        }
        *(float2*)(ACC + warp * 64 + 2 * lane) = make_float2(a0, a1);
    }
    __syncthreads();
    if (tid < 64) {
        float v = ACC[tid] + ACC[64 + tid] + ACC[128 + tid] + ACC[192 + tid]
                + ACC[256 + tid] + ACC[320 + tid] + ACC[384 + tid] + ACC[448 + tid];
        g_interest[(long)b * E_DIM + tid] = v / SV[1];
    }
}

// ---------------------------------------------------------------------------
// Kernel C: final MLP via bf16 MMA. 16 rows/CTA, 256 thr (8 warps), grid 256.
// GEMM1: M16 N256 K272 (warp owns n32); GEMM2: M16 N128 K256 (warp owns n16).
// B fragments loaded directly from pre-split globals (read once per CTA).
// smem (u32 words): AH[16][140] | AL[16][140] | H2H[16][132] | H2L[16][132]
//   | B1[256] | B2[128] | WO[128] | R[128]
// ---------------------------------------------------------------------------
#define MC_AH   0
#define MC_AL   2240
#define MC_H2H  4480
#define MC_H2L  (4480 + 2112)
#define MC_B1   (4480 + 4224)
#define MC_B2   (MC_B1 + 256)
#define MC_WO   (MC_B2 + 128)
#define MC_R    (MC_WO + 128)
#define SMEMC_WORDS (MC_R + 128)
#define SMEMC_BYTES (SMEMC_WORDS * 4)

__global__ void __launch_bounds__(256, 4)
din_mlp_kernel(const int* __restrict__ tgt,
               const int* __restrict__ sf,
               const float* __restrict__ dense,
               const float* __restrict__ item_table,
               const float* __restrict__ user_table,
               const float* __restrict__ ctx_table,
               const float* __restrict__ b1, const float* __restrict__ b2,
               const float* __restrict__ ow, const float* __restrict__ ob,
               float* __restrict__ out)
{
    extern __shared__ uint32_t smw[];
    uint32_t* AH  = smw + MC_AH;
    uint32_t* AL  = smw + MC_AL;
    uint32_t* H2H = smw + MC_H2H;
    uint32_t* H2L = smw + MC_H2L;
    float* B1S = (float*)(smw + MC_B1);
    float* B2S = (float*)(smw + MC_B2);
    float* WOS = (float*)(smw + MC_WO);
    float* R   = (float*)(smw + MC_R);

    const int b0   = blockIdx.x * 16;
    const int tid  = threadIdx.x;
    const int lane = tid & 31;
    const int wid  = tid >> 5;      // 0..7
    const int gid  = lane >> 2;     // 0..7
    const int tig  = lane & 3;      // 0..3

    // ---- stage features as packed bf16 hi/lo pairs ----
    for (int i = tid; i < 16 * 136; i += 256) {
        int bb = i / 136, w = i % 136;
        int gb = b0 + bb;
        int k = 2 * w;
        float e, o;
        if (k < 64) {
            const float* p = user_table + (long)sf[gb * 2] * 64 + k;
            e = p[0]; o = p[1];
        } else if (k < 128) {
            const float* p = ctx_table + (long)sf[gb * 2 + 1] * 64 + (k - 64);
            e = p[0]; o = p[1];
        } else if (k < 192) {
            const float* p = item_table + (long)tgt[gb] * 64 + (k - 128);
            e = p[0]; o = p[1];
        } else if (k < 256) {
            const float* p = g_interest + (long)gb * 64 + (k - 192);
            e = p[0]; o = p[1];
        } else {
            const float* p = dense + gb * 16 + (k - 256);
            e = p[0]; o = p[1];
        }
        uint32_t h, l;
        bsplit2(e, o, h, l);
        AH[bb * 140 + w] = h;
        AL[bb * 140 + w] = l;
    }
    if (tid < 256) B1S[tid] = b1[tid];
    if (tid < 128) { B2S[tid] = b2[tid]; WOS[tid] = ow[tid]; }
    __syncthreads();

    // ---- GEMM1: M16 x N256 x K272; warp owns n in [32*wid, 32*wid+32) ----
    const int n0 = wid * 32;
    {
        float acc[4][4];
        #pragma unroll
        for (int nt = 0; nt < 4; ++nt)
            #pragma unroll
            for (int p = 0; p < 4; ++p) acc[nt][p] = 0.f;

        for (int kc = 0; kc < 17; ++kc) {
            int a0 = gid * 140 + kc * 8 + tig;
            int a1 = (gid + 8) * 140 + kc * 8 + tig;
            uint32_t ah[4] = {AH[a0], AH[a1], AH[a0 + 4], AH[a1 + 4]};
            uint32_t al[4] = {AL[a0], AL[a1], AL[a0 + 4], AL[a1 + 4]};
            #pragma unroll
            for (int nt = 0; nt < 4; ++nt) {
                long boff = (long)(n0 + nt * 8 + gid) * 136 + kc * 8 + tig;
                uint32_t bh[2] = {g_m1H[boff], g_m1H[boff + 4]};
                uint32_t bl[2] = {g_m1L[boff], g_m1L[boff + 4]};
                mmabf(acc[nt], ah, bh);
                mmabf(acc[nt], ah, bl);
                mmabf(acc[nt], al, bh);
            }
        }
        // relu + b1, pack into H2 (k-pair layout for GEMM2's A, stride 132)
        #pragma unroll
        for (int nt = 0; nt < 4; ++nt) {
            int n = n0 + nt * 8 + 2 * tig;
            float q0 = B1S[n], q1 = B1S[n + 1];
            float v0 = fmaxf(acc[nt][0] + q0, 0.f);
            float v1 = fmaxf(acc[nt][1] + q1, 0.f);
            float v2 = fmaxf(acc[nt][2] + q0, 0.f);
            float v3 = fmaxf(acc[nt][3] + q1, 0.f);
            uint32_t h01, l01, h23, l23;
            bsplit2(v0, v1, h01, l01);
            bsplit2(v2, v3, h23, l23);
            int pw = (n0 >> 1) + nt * 4 + tig;      // pair index 0..127
            H2H[gid * 132 + pw]       = h01;
            H2L[gid * 132 + pw]       = l01;
            H2H[(gid + 8) * 132 + pw] = h23;
            H2L[(gid + 8) * 132 + pw] = l23;
        }
    }
    __syncthreads();

    // ---- GEMM2: M16 x N128 x K256; warp owns n in [16*wid, 16*wid+16) ----
    {
        const int n0b = wid * 16;
        float acc[2][4];
        #pragma unroll
        for (int nt = 0; nt < 2; ++nt)
            #pragma unroll
            for (int p = 0; p < 4; ++p) acc[nt][p] = 0.f;

        for (int kc = 0; kc < 16; ++kc) {
            int a0 = gid * 132 + kc * 8 + tig;
            int a1 = (gid + 8) * 132 + kc * 8 + tig;
            uint32_t ah[4] = {H2H[a0], H2H[a1], H2H[a0 + 4], H2H[a1 + 4]};
            uint32_t al[4] = {H2L[a0], H2L[a1], H2L[a0 + 4], H2L[a1 + 4]};
            #pragma unroll
            for (int nt = 0; nt < 2; ++nt) {
                long boff = (long)(n0b + nt * 8 + gid) * 128 + kc * 8 + tig;
                uint32_t bh[2] = {g_m2H[boff], g_m2H[boff + 4]};
                uint32_t bl[2] = {g_m2L[boff], g_m2L[boff + 4]};
                mmabf(acc[nt], ah, bh);
                mmabf(acc[nt], ah, bl);
                mmabf(acc[nt], al, bh);
            }
        }
        float s0 = 0.f, s8 = 0.f;
        #pragma unroll
        for (int nt = 0; nt < 2; ++nt) {
            int n = n0b + nt * 8 + 2 * tig;
            float bb0 = B2S[n], bb1 = B2S[n + 1];
            float w0 = WOS[n],  w1v = WOS[n + 1];
            s0 += fmaxf(acc[nt][0] + bb0, 0.f) * w0 + fmaxf(acc[nt][1] + bb1, 0.f) * w1v;
            s8 += fmaxf(acc[nt][2] + bb0, 0.f) * w0 + fmaxf(acc[nt][3] + bb1, 0.f) * w1v;
        }
        s0 += __shfl_xor_sync(0xffffffffu, s0, 1);
        s0 += __shfl_xor_sync(0xffffffffu, s0, 2);
        s8 += __shfl_xor_sync(0xffffffffu, s8, 1);
        s8 += __shfl_xor_sync(0xffffffffu, s8, 2);
        if (tig == 0) {
            R[wid * 16 + gid]     = s0;
            R[wid * 16 + gid + 8] = s8;
        }
    }
    __syncthreads();
    if (tid < 16) {
        float s = ob[0];
        #pragma unroll
        for (int w = 0; w < 8; ++w) s += R[w * 16 + tid];
        out[b0 + tid] = s;
    }
}

// ---------------------------------------------------------------------------
extern "C" void kernel_launch(void* const* d_in, const int* in_sizes, int n_in,
                              void* d_out, int out_size)
{
    const int*   tgt   = (const int*)d_in[0];
    const int*   hist  = (const int*)d_in[1];
    const int*   mask  = (const int*)d_in[2];
    const int*   sf    = (const int*)d_in[3];
    const float* dense = (const float*)d_in[4];
    const float* item_table = (const float*)d_in[5];
    const float* user_table = (const float*)d_in[6];
    const float* ctx_table  = (const float*)d_in[7];
    const float* att_w1 = (const float*)d_in[8];
    const float* att_b1 = (const float*)d_in[9];
    const float* att_w2 = (const float*)d_in[10];
    const float* att_b2 = (const float*)d_in[11];
    const float* att_wo = (const float*)d_in[12];
    const float* att_bo = (const float*)d_in[13];
    const float* mlp_w1 = (const float*)d_in[14];
    const float* mlp_b1 = (const float*)d_in[15];
    const float* mlp_w2 = (const float*)d_in[16];
    const float* mlp_b2 = (const float*)d_in[17];
    const float* out_w  = (const float*)d_in[18];
    const float* out_b  = (const float*)d_in[19];
    float*       out    = (float*)d_out;

    cudaFuncSetAttribute(din_scores_kernel, cudaFuncAttributeMaxDynamicSharedMemorySize, SMEMA_BYTES);
    cudaFuncSetAttribute(din_mlp_kernel,    cudaFuncAttributeMaxDynamicSharedMemorySize, SMEMC_BYTES);

    din_pack_kernel<<<(VOCAB_ITEM * 32 + 255) / 256, 256>>>(
        item_table, att_w2, mlp_w1, mlp_w2);

    din_fold_kernel<<<B_ROWS, 256>>>(tgt, item_table, att_w1, att_b1);

    din_scores_kernel<<<B_ROWS * 2, 256, SMEMA_BYTES>>>(
        tgt, hist, mask, att_b2, att_wo, att_bo);

    din_softmax_kernel<<<B_ROWS, 256>>>(hist, item_table);

    din_mlp_kernel<<<B_ROWS / 16, 256, SMEMC_BYTES>>>(
        tgt, sf, dense, item_table, user_table, ctx_table,
        mlp_b1, mlp_b2, out_w, out_b, out);
}

// round 15
// speedup vs baseline: 2.5112x; 1.0932x over previous
#include <cuda_runtime.h>
#include <cuda_bf16.h>
#include <cstdint>

// ---------------------------------------------------------------------------
// DIN forward.
//  Kernel PF: fused pre-split (item_table/w2/mlp weights) + per-b weight fold
//  Kernel A : scores via mma.sync bf16 m16n8k16, 3-pass hi/lo; asymmetric
//             t-tiles (128 rows / 80 rows) to skip padding MMAs
//  Kernel B : softmax + interest (coalesced row-major gather)
//  Kernel C : final MLP via bf16 MMA
// ---------------------------------------------------------------------------

#define B_ROWS 4096
#define T_LEN  200
#define TPAD   224
#define E_DIM  64
#define VOCAB_ITEM 100000
#define PACK_BLOCKS ((VOCAB_ITEM * 32 + 255) / 256)

__device__ uint32_t g_keyH[VOCAB_ITEM * 32];    // packed bf16-hi pairs per row
__device__ uint32_t g_keyL[VOCAB_ITEM * 32];    // packed bf16-lo pairs
__device__ uint32_t g_w12H[B_ROWS * 2048];      // [b][j][w] packed pairs
__device__ uint32_t g_w12L[B_ROWS * 2048];
__device__ uint32_t g_w2H[1024];                // [n][w]
__device__ uint32_t g_w2L[1024];
__device__ uint32_t g_m1H[256 * 136];           // mlp_w1 [n][w] packed pairs
__device__ uint32_t g_m1L[256 * 136];
__device__ uint32_t g_m2H[128 * 128];           // mlp_w2 [n][w]
__device__ uint32_t g_m2L[128 * 128];
__device__ float g_qc[B_ROWS * 64];
__device__ float g_scores[B_ROWS * TPAD];
__device__ float g_interest[B_ROWS * E_DIM];

// ---- bf16 split helpers ----
__device__ __forceinline__ void bsplit(float x, uint16_t& h, uint16_t& l) {
    __nv_bfloat16 bh = __float2bfloat16(x);
    float r = x - __bfloat162float(bh);
    __nv_bfloat16 bl = __float2bfloat16(r);
    h = *reinterpret_cast<uint16_t*>(&bh);
    l = *reinterpret_cast<uint16_t*>(&bl);
}
__device__ __forceinline__ uint32_t packu(uint16_t lo, uint16_t hi) {
    return (uint32_t)lo | ((uint32_t)hi << 16);
}
__device__ __forceinline__ void bsplit2(float e, float o, uint32_t& wh, uint32_t& wl) {
    uint16_t eh, el, oh, ol;
    bsplit(e, eh, el);
    bsplit(o, oh, ol);
    wh = packu(eh, oh);
    wl = packu(el, ol);
}

// D += A*B  (m16n8k16, A row-major, B col-major, bf16 in, f32 acc)
__device__ __forceinline__ void mmabf(float* d, const uint32_t* a, const uint32_t* b) {
    asm volatile(
        "mma.sync.aligned.m16n8k16.row.col.f32.bf16.bf16.f32 "
        "{%0,%1,%2,%3}, {%4,%5,%6,%7}, {%8,%9}, {%0,%1,%2,%3};"
        : "+f"(d[0]), "+f"(d[1]), "+f"(d[2]), "+f"(d[3])
        : "r"(a[0]), "r"(a[1]), "r"(a[2]), "r"(a[3]), "r"(b[0]), "r"(b[1]));
}

// ---------------------------------------------------------------------------
// Kernel PF: fused pack (blocks < PACK_BLOCKS) + fold (remaining B_ROWS blocks)
// ---------------------------------------------------------------------------
__global__ void __launch_bounds__(256)
din_prep_kernel(const int* __restrict__ tgt,
                const float* __restrict__ item_table,
                const float* __restrict__ w1, const float* __restrict__ b1,
                const float* __restrict__ w2,
                const float* __restrict__ m1,   // mlp_w1 [272][256]
                const float* __restrict__ m2)   // mlp_w2 [256][128]
{
    __shared__ float Q[64];
    __shared__ float SM[64 * 65];
    const int tid = threadIdx.x;

    if (blockIdx.x < PACK_BLOCKS) {
        // ---------------- pack part ----------------
        long i = (long)blockIdx.x * 256 + tid;
        if (i < (long)VOCAB_ITEM * 32) {
            float2 v = ((const float2*)item_table)[i];
            uint32_t h, l;
            bsplit2(v.x, v.y, h, l);
            g_keyH[i] = h;
            g_keyL[i] = l;
        }
        if (i < 1024) {
            int n = (int)i & 31, w = (int)i >> 5;
            float e = w2[(2 * w) * 32 + n];
            float o = w2[(2 * w + 1) * 32 + n];
            uint32_t h, l;
            bsplit2(e, o, h, l);
            g_w2H[n * 32 + w] = h;
            g_w2L[n * 32 + w] = l;
        }
        if (i < 256 * 136) {
            int n = (int)(i / 136), w = (int)(i % 136);
            float e = m1[(2 * w) * 256 + n];
            float o = m1[(2 * w + 1) * 256 + n];
            uint32_t h, l;
            bsplit2(e, o, h, l);
            g_m1H[i] = h;
            g_m1L[i] = l;
        }
        if (i < 128 * 128) {
            int n = (int)(i >> 7), w = (int)(i & 127);
            float e = m2[(2 * w) * 128 + n];
            float o = m2[(2 * w + 1) * 128 + n];
            uint32_t h, l;
            bsplit2(e, o, h, l);
            g_m2H[i] = h;
            g_m2L[i] = l;
        }
        return;
    }

    // ---------------- fold part ----------------
    const int b = blockIdx.x - PACK_BLOCKS;

    if (tid < 64) Q[tid] = item_table[(long)tgt[b] * 64 + tid];
    __syncthreads();

    for (int i = tid; i < 4096; i += 256) {
        int k = i >> 6, j = i & 63;
        SM[k * 65 + j] = w1[i] + w1[8192 + i] + Q[k] * w1[12288 + i];
    }
    __syncthreads();
    for (int i = tid; i < 2048; i += 256) {
        int j = i >> 5, w = i & 31;
        float e = SM[(2 * w) * 65 + j];
        float o = SM[(2 * w + 1) * 65 + j];
        uint32_t h, l;
        bsplit2(e, o, h, l);
        g_w12H[(long)b * 2048 + i] = h;
        g_w12L[(long)b * 2048 + i] = l;
    }
    if (tid < 64) {
        float s = b1[tid];
        #pragma unroll 8
        for (int e = 0; e < 64; ++e)
            s += Q[e] * (w1[4096 + e * 64 + tid] - w1[8192 + e * 64 + tid]);
        g_qc[b * 64 + tid] = s;
    }
}

// ---------------------------------------------------------------------------
// Kernel A: scores via mma.sync bf16 k16. grid = 2*B; tile0: 128 rows/8 warps,
// tile1: 80 rows/5 MMA warps (t in [128,208); t in [208,224) padded -1e9).
// ---------------------------------------------------------------------------
#define SA_KH    0
#define SA_KL    4608
#define SA_W12H  9216
#define SA_W12L  11520
#define SA_W2H   13824
#define SA_W2L   14976
#define SA_QC    16128
#define SA_B2    16192
#define SA_WO    16224
#define SMEMA_WORDS 16256
#define SMEMA_BYTES (SMEMA_WORDS * 4)

__global__ void __launch_bounds__(256, 3)
din_scores_kernel(const int* __restrict__ tgt,
                  const int* __restrict__ hist,
                  const int* __restrict__ mask,
                  const float* __restrict__ b2,
                  const float* __restrict__ wo, const float* __restrict__ bo)
{
    extern __shared__ uint32_t smu[];
    uint32_t* KH   = smu + SA_KH;     // aliased by H1H after A-frag hoist
    uint32_t* KL   = smu + SA_KL;     // aliased by H1L
    uint32_t* W12H = smu + SA_W12H;
    uint32_t* W12L = smu + SA_W12L;
    uint32_t* W2H  = smu + SA_W2H;
    uint32_t* W2L  = smu + SA_W2L;
    float*    QC   = (float*)(smu + SA_QC);
    float*    B2S  = (float*)(smu + SA_B2);
    float*    WOS  = (float*)(smu + SA_WO);

    const int b    = blockIdx.x >> 1;
    const int tile = blockIdx.x & 1;
    const int t0   = tile * 128;
    const int nrows = tile ? 80 : 128;   // staged local rows
    const int nw    = tile ? 5 : 8;      // warps doing MMA work
    const int tid  = threadIdx.x;
    const int lane = tid & 31;
    const int wid  = tid >> 5;      // 0..7
    const int gid  = lane >> 2;     // 0..7
    const int tig  = lane & 3;      // 0..3

    // ---- stage operands (pure copies) ----
    {
        const uint4* HV = (const uint4*)g_keyH;
        const uint4* LV = (const uint4*)g_keyL;
        for (int i = tid; i < nrows * 8; i += 256) {
            int f = i & 7, m = i >> 3;
            int tg = t0 + m;
            uint4 h = make_uint4(0u, 0u, 0u, 0u);
            uint4 l = make_uint4(0u, 0u, 0u, 0u);
            if (tg < T_LEN) {
                int row = hist[b * T_LEN + tg];
                h = HV[row * 8 + f];
                l = LV[row * 8 + f];
            }
            *(uint4*)(KH + m * 36 + 4 * f) = h;
            *(uint4*)(KL + m * 36 + 4 * f) = l;
        }
        const uint4* WH = (const uint4*)(g_w12H + (long)b * 2048);
        const uint4* WL = (const uint4*)(g_w12L + (long)b * 2048);
        for (int i = tid; i < 64 * 8; i += 256) {
            int f = i & 7, j = i >> 3;
            *(uint4*)(W12H + j * 36 + 4 * f) = WH[i];
            *(uint4*)(W12L + j * 36 + 4 * f) = WL[i];
        }
        const uint4* VH = (const uint4*)g_w2H;
        const uint4* VL = (const uint4*)g_w2L;
        {
            int i = tid;
            int f = i & 7, n = i >> 3;
            *(uint4*)(W2H + n * 36 + 4 * f) = VH[i];
            *(uint4*)(W2L + n * 36 + 4 * f) = VL[i];
        }
    }
    if (tid < 64) QC[tid] = g_qc[b * 64 + tid];
    if (tid < 32) { B2S[tid] = b2[tid]; WOS[tid] = wo[tid]; }
    if (tile == 1 && tid < 16)               // pad t in [208,224)
        g_scores[b * TPAD + 208 + tid] = -1e9f;
    __syncthreads();

    const int mb = wid * 16;

    // ---- GEMM1: H1[m][j] = relu(KEYS @ W12T^T + qc) ----
    uint32_t ah[4][4], al[4][4];
    if (wid < nw) {
        #pragma unroll
        for (int kc = 0; kc < 4; ++kc) {
            int a0 = (mb + gid) * 36 + kc * 8 + tig;
            int a1 = (mb + gid + 8) * 36 + kc * 8 + tig;
            ah[kc][0] = KH[a0]; ah[kc][1] = KH[a1];
            ah[kc][2] = KH[a0 + 4]; ah[kc][3] = KH[a1 + 4];
            al[kc][0] = KL[a0]; al[kc][1] = KL[a1];
            al[kc][2] = KL[a0 + 4]; al[kc][3] = KL[a1 + 4];
        }
    }
    __syncthreads();   // KEYS dead; smem becomes H1

    if (wid < nw) {
        #pragma unroll
        for (int nt = 0; nt < 8; ++nt) {
            float acc[4] = {0.f, 0.f, 0.f, 0.f};
            #pragma unroll
            for (int kc = 0; kc < 4; ++kc) {
                const int boff = (nt * 8 + gid) * 36 + kc * 8 + tig;
                uint32_t bh[2], bl[2];
                bh[0] = W12H[boff]; bh[1] = W12H[boff + 4];
                bl[0] = W12L[boff]; bl[1] = W12L[boff + 4];
                mmabf(acc, ah[kc], bh);
                mmabf(acc, ah[kc], bl);
                mmabf(acc, al[kc], bh);
            }
            int j0 = nt * 8 + 2 * tig;
            float q0 = QC[j0], q1 = QC[j0 + 1];
            float v0 = fmaxf(acc[0] + q0, 0.f);
            float v1 = fmaxf(acc[1] + q1, 0.f);
            float v2 = fmaxf(acc[2] + q0, 0.f);
            float v3 = fmaxf(acc[3] + q1, 0.f);
            uint32_t h01, l01, h23, l23;
            bsplit2(v0, v1, h01, l01);
            bsplit2(v2, v3, h23, l23);
            KH[(mb + gid) * 36 + nt * 4 + tig]     = h01;  // H1H
            KL[(mb + gid) * 36 + nt * 4 + tig]     = l01;  // H1L
            KH[(mb + gid + 8) * 36 + nt * 4 + tig] = h23;
            KL[(mb + gid + 8) * 36 + nt * 4 + tig] = l23;
        }
        __syncwarp();   // H1 rows are warp-private

        // ---- GEMM2: scores = reduce_n relu(H1 @ W2T^T + b2)*wo ----
        uint32_t ch[4][4], cl[4][4];
        #pragma unroll
        for (int kc = 0; kc < 4; ++kc) {
            int a0 = (mb + gid) * 36 + kc * 8 + tig;
            int a1 = (mb + gid + 8) * 36 + kc * 8 + tig;
            ch[kc][0] = KH[a0]; ch[kc][1] = KH[a1];
            ch[kc][2] = KH[a0 + 4]; ch[kc][3] = KH[a1 + 4];
            cl[kc][0] = KL[a0]; cl[kc][1] = KL[a1];
            cl[kc][2] = KL[a0 + 4]; cl[kc][3] = KL[a1 + 4];
        }
        float srow0 = 0.f, srow8 = 0.f;
        #pragma unroll
        for (int nt = 0; nt < 4; ++nt) {
            float acc[4] = {0.f, 0.f, 0.f, 0.f};
            #pragma unroll
            for (int kc = 0; kc < 4; ++kc) {
                const int boff = (nt * 8 + gid) * 36 + kc * 8 + tig;
                uint32_t bh[2], bl[2];
                bh[0] = W2H[boff]; bh[1] = W2H[boff + 4];
                bl[0] = W2L[boff]; bl[1] = W2L[boff + 4];
                mmabf(acc, ch[kc], bh);
                mmabf(acc, ch[kc], bl);
                mmabf(acc, cl[kc], bh);
            }
            int n0 = nt * 8 + 2 * tig;
            float bb0 = B2S[n0], bb1 = B2S[n0 + 1];
            float w0 = WOS[n0],  w1v = WOS[n0 + 1];
            srow0 += fmaxf(acc[0] + bb0, 0.f) * w0 + fmaxf(acc[1] + bb1, 0.f) * w1v;
            srow8 += fmaxf(acc[2] + bb0, 0.f) * w0 + fmaxf(acc[3] + bb1, 0.f) * w1v;
        }
        srow0 += __shfl_xor_sync(0xffffffffu, srow0, 1);
        srow0 += __shfl_xor_sync(0xffffffffu, srow0, 2);
        srow8 += __shfl_xor_sync(0xffffffffu, srow8, 1);
        srow8 += __shfl_xor_sync(0xffffffffu, srow8, 2);

        if (tig == 0) {
            float bos = bo[0];
            int tg0 = t0 + mb + gid;
            int tg8 = tg0 + 8;
            if (tg0 < T_LEN)
                g_scores[b * TPAD + tg0] = mask[b * T_LEN + tg0] ? srow0 + bos : -1e9f;
            else if (tg0 < TPAD)
                g_scores[b * TPAD + tg0] = -1e9f;
            if (tg8 < T_LEN)
                g_scores[b * TPAD + tg8] = mask[b * T_LEN + tg8] ? srow8 + bos : -1e9f;
            else if (tg8 < TPAD)
                g_scores[b * TPAD + tg8] = -1e9f;
        }
    }
}

// ---------------------------------------------------------------------------
// Kernel B: softmax over 224 scores + interest (coalesced gather).
// ---------------------------------------------------------------------------
__global__ void __launch_bounds__(256, 8)
din_softmax_kernel(const int* __restrict__ hist,
                   const float* __restrict__ item_table)
{
    __shared__ float SC[TPAD];
    __shared__ float WG[TPAD];
    __shared__ float RED[8];
    __shared__ float SV[2];
    __shared__ float ACC[8 * 64];

    const int b    = blockIdx.x;
    const int tid  = threadIdx.x;
    const int lane = tid & 31;
    const int warp = tid >> 5;

    float s = (tid < TPAD) ? g_scores[b * TPAD + tid] : -3.4e38f;
    if (tid < TPAD) SC[tid] = s;

    float m = s;
    #pragma unroll
    for (int off = 16; off > 0; off >>= 1)
        m = fmaxf(m, __shfl_xor_sync(0xffffffffu, m, off));
    if (lane == 0) RED[warp] = m;
    __syncthreads();
    if (warp == 0) {
        float mm = (lane < 7) ? RED[lane] : -3.4e38f;
        #pragma unroll
        for (int off = 4; off > 0; off >>= 1)
            mm = fmaxf(mm, __shfl_xor_sync(0xffffffffu, mm, off));
        if (lane == 0) SV[0] = mm;
    }
    __syncthreads();

    float e = 0.f;
    if (tid < TPAD) {
        e = expf(SC[tid] - SV[0]);
        WG[tid] = e;
    }
    #pragma unroll
    for (int off = 16; off > 0; off >>= 1)
        e += __shfl_xor_sync(0xffffffffu, e, off);
    if (lane == 0) RED[warp] = e;
    __syncthreads();
    if (warp == 0) {
        float t2 = (lane < 7) ? RED[lane] : 0.f;
        #pragma unroll
        for (int off = 4; off > 0; off >>= 1)
            t2 += __shfl_xor_sync(0xffffffffu, t2, off);
        if (lane == 0) SV[1] = t2;
    }
    __syncthreads();

    {
        float a0 = 0.f, a1 = 0.f;
        #pragma unroll 5
        for (int i = 0; i < 25; ++i) {
            int t = warp + 8 * i;           // 8*25 = 200 exactly
            float wv = WG[t];
            int row = hist[b * T_LEN + t];
            float2 v = *(const float2*)(item_table + (long)row * E_DIM + 2 * lane);
            a0 += wv * v.x;
            a1 += wv * v.y;
        }
        *(float2*)(ACC + warp * 64 + 2 * lane) = make_float2(a0, a1);
    }
    __syncthreads();
    if (tid < 64) {
        float v = ACC[tid] + ACC[64 + tid] + ACC[128 + tid] + ACC[192 + tid]
                + ACC[256 + tid] + ACC[320 + tid] + ACC[384 + tid] + ACC[448 + tid];
        g_interest[(long)b * E_DIM + tid] = v / SV[1];
    }
}

// ---------------------------------------------------------------------------
// Kernel C: final MLP via bf16 MMA. 16 rows/CTA, 256 thr (8 warps), grid 256.
// ---------------------------------------------------------------------------
#define MC_AH   0
#define MC_AL   2240
#define MC_H2H  4480
#define MC_H2L  (4480 + 2112)
#define MC_B1   (4480 + 4224)
#define MC_B2   (MC_B1 + 256)
#define MC_WO   (MC_B2 + 128)
#define MC_R    (MC_WO + 128)
#define SMEMC_WORDS (MC_R + 128)
#define SMEMC_BYTES (SMEMC_WORDS * 4)

__global__ void __launch_bounds__(256, 4)
din_mlp_kernel(const int* __restrict__ tgt,
               const int* __restrict__ sf,
               const float* __restrict__ dense,
               const float* __restrict__ item_table,
               const float* __restrict__ user_table,
               const float* __restrict__ ctx_table,
               const float* __restrict__ b1, const float* __restrict__ b2,
               const float* __restrict__ ow, const float* __restrict__ ob,
               float* __restrict__ out)
{
    extern __shared__ uint32_t smw[];
    uint32_t* AH  = smw + MC_AH;
    uint32_t* AL  = smw + MC_AL;
    uint32_t* H2H = smw + MC_H2H;
    uint32_t* H2L = smw + MC_H2L;
    float* B1S = (float*)(smw + MC_B1);
    float* B2S = (float*)(smw + MC_B2);
    float* WOS = (float*)(smw + MC_WO);
    float* R   = (float*)(smw + MC_R);

    const int b0   = blockIdx.x * 16;
    const int tid  = threadIdx.x;
    const int lane = tid & 31;
    const int wid  = tid >> 5;      // 0..7
    const int gid  = lane >> 2;     // 0..7
    const int tig  = lane & 3;      // 0..3

    // ---- stage features as packed bf16 hi/lo pairs ----
    for (int i = tid; i < 16 * 136; i += 256) {
        int bb = i / 136, w = i % 136;
        int gb = b0 + bb;
        int k = 2 * w;
        float e, o;
        if (k < 64) {
            const float* p = user_table + (long)sf[gb * 2] * 64 + k;
            e = p[0]; o = p[1];
        } else if (k < 128) {
            const float* p = ctx_table + (long)sf[gb * 2 + 1] * 64 + (k - 64);
            e = p[0]; o = p[1];
        } else if (k < 192) {
            const float* p = item_table + (long)tgt[gb] * 64 + (k - 128);
            e = p[0]; o = p[1];
        } else if (k < 256) {
            const float* p = g_interest + (long)gb * 64 + (k - 192);
            e = p[0]; o = p[1];
        } else {
            const float* p = dense + gb * 16 + (k - 256);
            e = p[0]; o = p[1];
        }
        uint32_t h, l;
        bsplit2(e, o, h, l);
        AH[bb * 140 + w] = h;
        AL[bb * 140 + w] = l;
    }
    if (tid < 256) B1S[tid] = b1[tid];
    if (tid < 128) { B2S[tid] = b2[tid]; WOS[tid] = ow[tid]; }
    __syncthreads();

    // ---- GEMM1: M16 x N256 x K272; warp owns n in [32*wid, 32*wid+32) ----
    const int n0 = wid * 32;
    {
        float acc[4][4];
        #pragma unroll
        for (int nt = 0; nt < 4; ++nt)
            #pragma unroll
            for (int p = 0; p < 4; ++p) acc[nt][p] = 0.f;

        for (int kc = 0; kc < 17; ++kc) {
            int a0 = gid * 140 + kc * 8 + tig;
            int a1 = (gid + 8) * 140 + kc * 8 + tig;
            uint32_t ah[4] = {AH[a0], AH[a1], AH[a0 + 4], AH[a1 + 4]};
            uint32_t al[4] = {AL[a0], AL[a1], AL[a0 + 4], AL[a1 + 4]};
            #pragma unroll
            for (int nt = 0; nt < 4; ++nt) {
                long boff = (long)(n0 + nt * 8 + gid) * 136 + kc * 8 + tig;
                uint32_t bh[2] = {g_m1H[boff], g_m1H[boff + 4]};
                uint32_t bl[2] = {g_m1L[boff], g_m1L[boff + 4]};
                mmabf(acc[nt], ah, bh);
                mmabf(acc[nt], ah, bl);
                mmabf(acc[nt], al, bh);
            }
        }
        // relu + b1, pack into H2 (k-pair layout for GEMM2's A, stride 132)
        #pragma unroll
        for (int nt = 0; nt < 4; ++nt) {
            int n = n0 + nt * 8 + 2 * tig;
            float q0 = B1S[n], q1 = B1S[n + 1];
            float v0 = fmaxf(acc[nt][0] + q0, 0.f);
            float v1 = fmaxf(acc[nt][1] + q1, 0.f);
            float v2 = fmaxf(acc[nt][2] + q0, 0.f);
            float v3 = fmaxf(acc[nt][3] + q1, 0.f);
            uint32_t h01, l01, h23, l23;
            bsplit2(v0, v1, h01, l01);
            bsplit2(v2, v3, h23, l23);
            int pw = (n0 >> 1) + nt * 4 + tig;      // pair index 0..127
            H2H[gid * 132 + pw]       = h01;
            H2L[gid * 132 + pw]       = l01;
            H2H[(gid + 8) * 132 + pw] = h23;
            H2L[(gid + 8) * 132 + pw] = l23;
        }
    }
    __syncthreads();

    // ---- GEMM2: M16 x N128 x K256; warp owns n in [16*wid, 16*wid+16) ----
    {
        const int n0b = wid * 16;
        float acc[2][4];
        #pragma unroll
        for (int nt = 0; nt < 2; ++nt)
            #pragma unroll
            for (int p = 0; p < 4; ++p) acc[nt][p] = 0.f;

        for (int kc = 0; kc < 16; ++kc) {
            int a0 = gid * 132 + kc * 8 + tig;
            int a1 = (gid + 8) * 132 + kc * 8 + tig;
            uint32_t ah[4] = {H2H[a0], H2H[a1], H2H[a0 + 4], H2H[a1 + 4]};
            uint32_t al[4] = {H2L[a0], H2L[a1], H2L[a0 + 4], H2L[a1 + 4]};
            #pragma unroll
            for (int nt = 0; nt < 2; ++nt) {
                long boff = (long)(n0b + nt * 8 + gid) * 128 + kc * 8 + tig;
                uint32_t bh[2] = {g_m2H[boff], g_m2H[boff + 4]};
                uint32_t bl[2] = {g_m2L[boff], g_m2L[boff + 4]};
                mmabf(acc[nt], ah, bh);
                mmabf(acc[nt], ah, bl);
                mmabf(acc[nt], al, bh);
            }
        }
        float s0 = 0.f, s8 = 0.f;
        #pragma unroll
        for (int nt = 0; nt < 2; ++nt) {
            int n = n0b + nt * 8 + 2 * tig;
            float bb0 = B2S[n], bb1 = B2S[n + 1];
            float w0 = WOS[n],  w1v = WOS[n + 1];
            s0 += fmaxf(acc[nt][0] + bb0, 0.f) * w0 + fmaxf(acc[nt][1] + bb1, 0.f) * w1v;
            s8 += fmaxf(acc[nt][2] + bb0, 0.f) * w0 + fmaxf(acc[nt][3] + bb1, 0.f) * w1v;
        }
        s0 += __shfl_xor_sync(0xffffffffu, s0, 1);
        s0 += __shfl_xor_sync(0xffffffffu, s0, 2);
        s8 += __shfl_xor_sync(0xffffffffu, s8, 1);
        s8 += __shfl_xor_sync(0xffffffffu, s8, 2);
        if (tig == 0) {
            R[wid * 16 + gid]     = s0;
            R[wid * 16 + gid + 8] = s8;
        }
    }
    __syncthreads();
    if (tid < 16) {
        float s = ob[0];
        #pragma unroll
        for (int w = 0; w < 8; ++w) s += R[w * 16 + tid];
        out[b0 + tid] = s;
    }
}

// ---------------------------------------------------------------------------
extern "C" void kernel_launch(void* const* d_in, const int* in_sizes, int n_in,
                              void* d_out, int out_size)
{
    const int*   tgt   = (const int*)d_in[0];
    const int*   hist  = (const int*)d_in[1];
    const int*   mask  = (const int*)d_in[2];
    const int*   sf    = (const int*)d_in[3];
    const float* dense = (const float*)d_in[4];
    const float* item_table = (const float*)d_in[5];
    const float* user_table = (const float*)d_in[6];
    const float* ctx_table  = (const float*)d_in[7];
    const float* att_w1 = (const float*)d_in[8];
    const float* att_b1 = (const float*)d_in[9];
    const float* att_w2 = (const float*)d_in[10];
    const float* att_b2 = (const float*)d_in[11];
    const float* att_wo = (const float*)d_in[12];
    const float* att_bo = (const float*)d_in[13];
    const float* mlp_w1 = (const float*)d_in[14];
    const float* mlp_b1 = (const float*)d_in[15];
    const float* mlp_w2 = (const float*)d_in[16];
    const float* mlp_b2 = (const float*)d_in[17];
    const float* out_w  = (const float*)d_in[18];
    const float* out_b  = (const float*)d_in[19];
    float*       out    = (float*)d_out;

    cudaFuncSetAttribute(din_scores_kernel, cudaFuncAttributeMaxDynamicSharedMemorySize, SMEMA_BYTES);
    cudaFuncSetAttribute(din_mlp_kernel,    cudaFuncAttributeMaxDynamicSharedMemorySize, SMEMC_BYTES);

    din_prep_kernel<<<PACK_BLOCKS + B_ROWS, 256>>>(
        tgt, item_table, att_w1, att_b1, att_w2, mlp_w1, mlp_w2);

    din_scores_kernel<<<B_ROWS * 2, 256, SMEMA_BYTES>>>(
        tgt, hist, mask, att_b2, att_wo, att_bo);

    din_softmax_kernel<<<B_ROWS, 256>>>(hist, item_table);

    din_mlp_kernel<<<B_ROWS / 16, 256, SMEMC_BYTES>>>(
        tgt, sf, dense, item_table, user_table, ctx_table,
        mlp_b1, mlp_b2, out_w, out_b, out);
}

// round 16
// speedup vs baseline: 2.5209x; 1.0039x over previous
#include <cuda_runtime.h>
#include <cuda_bf16.h>
#include <cstdint>

// ---------------------------------------------------------------------------
// DIN forward.
//  Kernel PF: fused pre-split (item_table/w2/mlp weights) + per-b weight fold
//  Kernel A : scores via mma.sync bf16 m16n8k16, 3-pass hi/lo; asymmetric
//             t-tiles (128 rows / 80 rows) to skip padding MMAs
//  Kernel B : softmax + interest (coalesced row-major gather)
//  Kernel C : final MLP via bf16 MMA, B-fragment software pipelining
// ---------------------------------------------------------------------------

#define B_ROWS 4096
#define T_LEN  200
#define TPAD   224
#define E_DIM  64
#define VOCAB_ITEM 100000
#define PACK_BLOCKS ((VOCAB_ITEM * 32 + 255) / 256)

__device__ uint32_t g_keyH[VOCAB_ITEM * 32];    // packed bf16-hi pairs per row
__device__ uint32_t g_keyL[VOCAB_ITEM * 32];    // packed bf16-lo pairs
__device__ uint32_t g_w12H[B_ROWS * 2048];      // [b][j][w] packed pairs
__device__ uint32_t g_w12L[B_ROWS * 2048];
__device__ uint32_t g_w2H[1024];                // [n][w]
__device__ uint32_t g_w2L[1024];
__device__ uint32_t g_m1H[256 * 136];           // mlp_w1 [n][w] packed pairs
__device__ uint32_t g_m1L[256 * 136];
__device__ uint32_t g_m2H[128 * 128];           // mlp_w2 [n][w]
__device__ uint32_t g_m2L[128 * 128];
__device__ float g_qc[B_ROWS * 64];
__device__ float g_scores[B_ROWS * TPAD];
__device__ float g_interest[B_ROWS * E_DIM];

// ---- bf16 split helpers ----
__device__ __forceinline__ void bsplit(float x, uint16_t& h, uint16_t& l) {
    __nv_bfloat16 bh = __float2bfloat16(x);
    float r = x - __bfloat162float(bh);
    __nv_bfloat16 bl = __float2bfloat16(r);
    h = *reinterpret_cast<uint16_t*>(&bh);
    l = *reinterpret_cast<uint16_t*>(&bl);
}
__device__ __forceinline__ uint32_t packu(uint16_t lo, uint16_t hi) {
    return (uint32_t)lo | ((uint32_t)hi << 16);
}
__device__ __forceinline__ void bsplit2(float e, float o, uint32_t& wh, uint32_t& wl) {
    uint16_t eh, el, oh, ol;
    bsplit(e, eh, el);
    bsplit(o, oh, ol);
    wh = packu(eh, oh);
    wl = packu(el, ol);
}

// D += A*B  (m16n8k16, A row-major, B col-major, bf16 in, f32 acc)
__device__ __forceinline__ void mmabf(float* d, const uint32_t* a, const uint32_t* b) {
    asm volatile(
        "mma.sync.aligned.m16n8k16.row.col.f32.bf16.bf16.f32 "
        "{%0,%1,%2,%3}, {%4,%5,%6,%7}, {%8,%9}, {%0,%1,%2,%3};"
        : "+f"(d[0]), "+f"(d[1]), "+f"(d[2]), "+f"(d[3])
        : "r"(a[0]), "r"(a[1]), "r"(a[2]), "r"(a[3]), "r"(b[0]), "r"(b[1]));
}

// ---------------------------------------------------------------------------
// Kernel PF: fused pack (blocks < PACK_BLOCKS) + fold (remaining B_ROWS blocks)
// ---------------------------------------------------------------------------
__global__ void __launch_bounds__(256)
din_prep_kernel(const int* __restrict__ tgt,
                const float* __restrict__ item_table,
                const float* __restrict__ w1, const float* __restrict__ b1,
                const float* __restrict__ w2,
                const float* __restrict__ m1,   // mlp_w1 [272][256]
                const float* __restrict__ m2)   // mlp_w2 [256][128]
{
    __shared__ float Q[64];
    __shared__ float SM[64 * 65];
    const int tid = threadIdx.x;

    if (blockIdx.x < PACK_BLOCKS) {
        long i = (long)blockIdx.x * 256 + tid;
        if (i < (long)VOCAB_ITEM * 32) {
            float2 v = ((const float2*)item_table)[i];
            uint32_t h, l;
            bsplit2(v.x, v.y, h, l);
            g_keyH[i] = h;
            g_keyL[i] = l;
        }
        if (i < 1024) {
            int n = (int)i & 31, w = (int)i >> 5;
            float e = w2[(2 * w) * 32 + n];
            float o = w2[(2 * w + 1) * 32 + n];
            uint32_t h, l;
            bsplit2(e, o, h, l);
            g_w2H[n * 32 + w] = h;
            g_w2L[n * 32 + w] = l;
        }
        if (i < 256 * 136) {
            int n = (int)(i / 136), w = (int)(i % 136);
            float e = m1[(2 * w) * 256 + n];
            float o = m1[(2 * w + 1) * 256 + n];
            uint32_t h, l;
            bsplit2(e, o, h, l);
            g_m1H[i] = h;
            g_m1L[i] = l;
        }
        if (i < 128 * 128) {
            int n = (int)(i >> 7), w = (int)(i & 127);
            float e = m2[(2 * w) * 128 + n];
            float o = m2[(2 * w + 1) * 128 + n];
            uint32_t h, l;
            bsplit2(e, o, h, l);
            g_m2H[i] = h;
            g_m2L[i] = l;
        }
        return;
    }

    const int b = blockIdx.x - PACK_BLOCKS;

    if (tid < 64) Q[tid] = item_table[(long)tgt[b] * 64 + tid];
    __syncthreads();

    for (int i = tid; i < 4096; i += 256) {
        int k = i >> 6, j = i & 63;
        SM[k * 65 + j] = w1[i] + w1[8192 + i] + Q[k] * w1[12288 + i];
    }
    __syncthreads();
    for (int i = tid; i < 2048; i += 256) {
        int j = i >> 5, w = i & 31;
        float e = SM[(2 * w) * 65 + j];
        float o = SM[(2 * w + 1) * 65 + j];
        uint32_t h, l;
        bsplit2(e, o, h, l);
        g_w12H[(long)b * 2048 + i] = h;
        g_w12L[(long)b * 2048 + i] = l;
    }
    if (tid < 64) {
        float s = b1[tid];
        #pragma unroll 8
        for (int e = 0; e < 64; ++e)
            s += Q[e] * (w1[4096 + e * 64 + tid] - w1[8192 + e * 64 + tid]);
        g_qc[b * 64 + tid] = s;
    }
}

// ---------------------------------------------------------------------------
// Kernel A: scores via mma.sync bf16 k16. grid = 2*B; tile0: 128 rows/8 warps,
// tile1: 80 rows/5 MMA warps (t in [128,208); t in [208,224) padded -1e9).
// ---------------------------------------------------------------------------
#define SA_KH    0
#define SA_KL    4608
#define SA_W12H  9216
#define SA_W12L  11520
#define SA_W2H   13824
#define SA_W2L   14976
#define SA_QC    16128
#define SA_B2    16192
#define SA_WO    16224
#define SMEMA_WORDS 16256
#define SMEMA_BYTES (SMEMA_WORDS * 4)

__global__ void __launch_bounds__(256, 3)
din_scores_kernel(const int* __restrict__ tgt,
                  const int* __restrict__ hist,
                  const int* __restrict__ mask,
                  const float* __restrict__ b2,
                  const float* __restrict__ wo, const float* __restrict__ bo)
{
    extern __shared__ uint32_t smu[];
    uint32_t* KH   = smu + SA_KH;     // aliased by H1H after A-frag hoist
    uint32_t* KL   = smu + SA_KL;     // aliased by H1L
    uint32_t* W12H = smu + SA_W12H;
    uint32_t* W12L = smu + SA_W12L;
    uint32_t* W2H  = smu + SA_W2H;
    uint32_t* W2L  = smu + SA_W2L;
    float*    QC   = (float*)(smu + SA_QC);
    float*    B2S  = (float*)(smu + SA_B2);
    float*    WOS  = (float*)(smu + SA_WO);

    const int b    = blockIdx.x >> 1;
    const int tile = blockIdx.x & 1;
    const int t0   = tile * 128;
    const int nrows = tile ? 80 : 128;   // staged local rows
    const int nw    = tile ? 5 : 8;      // warps doing MMA work
    const int tid  = threadIdx.x;
    const int lane = tid & 31;
    const int wid  = tid >> 5;      // 0..7
    const int gid  = lane >> 2;     // 0..7
    const int tig  = lane & 3;      // 0..3

    // ---- stage operands (pure copies) ----
    {
        const uint4* HV = (const uint4*)g_keyH;
        const uint4* LV = (const uint4*)g_keyL;
        for (int i = tid; i < nrows * 8; i += 256) {
            int f = i & 7, m = i >> 3;
            int tg = t0 + m;
            uint4 h = make_uint4(0u, 0u, 0u, 0u);
            uint4 l = make_uint4(0u, 0u, 0u, 0u);
            if (tg < T_LEN) {
                int row = hist[b * T_LEN + tg];
                h = HV[row * 8 + f];
                l = LV[row * 8 + f];
            }
            *(uint4*)(KH + m * 36 + 4 * f) = h;
            *(uint4*)(KL + m * 36 + 4 * f) = l;
        }
        const uint4* WH = (const uint4*)(g_w12H + (long)b * 2048);
        const uint4* WL = (const uint4*)(g_w12L + (long)b * 2048);
        for (int i = tid; i < 64 * 8; i += 256) {
            int f = i & 7, j = i >> 3;
            *(uint4*)(W12H + j * 36 + 4 * f) = WH[i];
            *(uint4*)(W12L + j * 36 + 4 * f) = WL[i];
        }
        const uint4* VH = (const uint4*)g_w2H;
        const uint4* VL = (const uint4*)g_w2L;
        {
            int i = tid;
            int f = i & 7, n = i >> 3;
            *(uint4*)(W2H + n * 36 + 4 * f) = VH[i];
            *(uint4*)(W2L + n * 36 + 4 * f) = VL[i];
        }
    }
    if (tid < 64) QC[tid] = g_qc[b * 64 + tid];
    if (tid < 32) { B2S[tid] = b2[tid]; WOS[tid] = wo[tid]; }
    if (tile == 1 && tid < 16)               // pad t in [208,224)
        g_scores[b * TPAD + 208 + tid] = -1e9f;
    __syncthreads();

    const int mb = wid * 16;

    // ---- GEMM1: H1[m][j] = relu(KEYS @ W12T^T + qc) ----
    uint32_t ah[4][4], al[4][4];
    if (wid < nw) {
        #pragma unroll
        for (int kc = 0; kc < 4; ++kc) {
            int a0 = (mb + gid) * 36 + kc * 8 + tig;
            int a1 = (mb + gid + 8) * 36 + kc * 8 + tig;
            ah[kc][0] = KH[a0]; ah[kc][1] = KH[a1];
            ah[kc][2] = KH[a0 + 4]; ah[kc][3] = KH[a1 + 4];
            al[kc][0] = KL[a0]; al[kc][1] = KL[a1];
            al[kc][2] = KL[a0 + 4]; al[kc][3] = KL[a1 + 4];
        }
    }
    __syncthreads();   // KEYS dead; smem becomes H1

    if (wid < nw) {
        #pragma unroll
        for (int nt = 0; nt < 8; ++nt) {
            float acc[4] = {0.f, 0.f, 0.f, 0.f};
            #pragma unroll
            for (int kc = 0; kc < 4; ++kc) {
                const int boff = (nt * 8 + gid) * 36 + kc * 8 + tig;
                uint32_t bh[2], bl[2];
                bh[0] = W12H[boff]; bh[1] = W12H[boff + 4];
                bl[0] = W12L[boff]; bl[1] = W12L[boff + 4];
                mmabf(acc, ah[kc], bh);
                mmabf(acc, ah[kc], bl);
                mmabf(acc, al[kc], bh);
            }
            int j0 = nt * 8 + 2 * tig;
            float q0 = QC[j0], q1 = QC[j0 + 1];
            float v0 = fmaxf(acc[0] + q0, 0.f);
            float v1 = fmaxf(acc[1] + q1, 0.f);
            float v2 = fmaxf(acc[2] + q0, 0.f);
            float v3 = fmaxf(acc[3] + q1, 0.f);
            uint32_t h01, l01, h23, l23;
            bsplit2(v0, v1, h01, l01);
            bsplit2(v2, v3, h23, l23);
            KH[(mb + gid) * 36 + nt * 4 + tig]     = h01;  // H1H
            KL[(mb + gid) * 36 + nt * 4 + tig]     = l01;  // H1L
            KH[(mb + gid + 8) * 36 + nt * 4 + tig] = h23;
            KL[(mb + gid + 8) * 36 + nt * 4 + tig] = l23;
        }
        __syncwarp();   // H1 rows are warp-private

        // ---- GEMM2: scores = reduce_n relu(H1 @ W2T^T + b2)*wo ----
        uint32_t ch[4][4], cl[4][4];
        #pragma unroll
        for (int kc = 0; kc < 4; ++kc) {
            int a0 = (mb + gid) * 36 + kc * 8 + tig;
            int a1 = (mb + gid + 8) * 36 + kc * 8 + tig;
            ch[kc][0] = KH[a0]; ch[kc][1] = KH[a1];
            ch[kc][2] = KH[a0 + 4]; ch[kc][3] = KH[a1 + 4];
            cl[kc][0] = KL[a0]; cl[kc][1] = KL[a1];
            cl[kc][2] = KL[a0 + 4]; cl[kc][3] = KL[a1 + 4];
        }
        float srow0 = 0.f, srow8 = 0.f;
        #pragma unroll
        for (int nt = 0; nt < 4; ++nt) {
            float acc[4] = {0.f, 0.f, 0.f, 0.f};
            #pragma unroll
            for (int kc = 0; kc < 4; ++kc) {
                const int boff = (nt * 8 + gid) * 36 + kc * 8 + tig;
                uint32_t bh[2], bl[2];
                bh[0] = W2H[boff]; bh[1] = W2H[boff + 4];
                bl[0] = W2L[boff]; bl[1] = W2L[boff + 4];
                mmabf(acc, ch[kc], bh);
                mmabf(acc, ch[kc], bl);
                mmabf(acc, cl[kc], bh);
            }
            int n0 = nt * 8 + 2 * tig;
            float bb0 = B2S[n0], bb1 = B2S[n0 + 1];
            float w0 = WOS[n0],  w1v = WOS[n0 + 1];
            srow0 += fmaxf(acc[0] + bb0, 0.f) * w0 + fmaxf(acc[1] + bb1, 0.f) * w1v;
            srow8 += fmaxf(acc[2] + bb0, 0.f) * w0 + fmaxf(acc[3] + bb1, 0.f) * w1v;
        }
        srow0 += __shfl_xor_sync(0xffffffffu, srow0, 1);
        srow0 += __shfl_xor_sync(0xffffffffu, srow0, 2);
        srow8 += __shfl_xor_sync(0xffffffffu, srow8, 1);
        srow8 += __shfl_xor_sync(0xffffffffu, srow8, 2);

        if (tig == 0) {
            float bos = bo[0];
            int tg0 = t0 + mb + gid;
            int tg8 = tg0 + 8;
            if (tg0 < T_LEN)
                g_scores[b * TPAD + tg0] = mask[b * T_LEN + tg0] ? srow0 + bos : -1e9f;
            else if (tg0 < TPAD)
                g_scores[b * TPAD + tg0] = -1e9f;
            if (tg8 < T_LEN)
                g_scores[b * TPAD + tg8] = mask[b * T_LEN + tg8] ? srow8 + bos : -1e9f;
            else if (tg8 < TPAD)
                g_scores[b * TPAD + tg8] = -1e9f;
        }
    }
}

// ---------------------------------------------------------------------------
// Kernel B: softmax over 224 scores + interest (coalesced gather).
// ---------------------------------------------------------------------------
__global__ void __launch_bounds__(256, 8)
din_softmax_kernel(const int* __restrict__ hist,
                   const float* __restrict__ item_table)
{
    __shared__ float SC[TPAD];
    __shared__ float WG[TPAD];
    __shared__ float RED[8];
    __shared__ float SV[2];
    __shared__ float ACC[8 * 64];

    const int b    = blockIdx.x;
    const int tid  = threadIdx.x;
    const int lane = tid & 31;
    const int warp = tid >> 5;

    float s = (tid < TPAD) ? g_scores[b * TPAD + tid] : -3.4e38f;
    if (tid < TPAD) SC[tid] = s;

    float m = s;
    #pragma unroll
    for (int off = 16; off > 0; off >>= 1)
        m = fmaxf(m, __shfl_xor_sync(0xffffffffu, m, off));
    if (lane == 0) RED[warp] = m;
    __syncthreads();
    if (warp == 0) {
        float mm = (lane < 7) ? RED[lane] : -3.4e38f;
        #pragma unroll
        for (int off = 4; off > 0; off >>= 1)
            mm = fmaxf(mm, __shfl_xor_sync(0xffffffffu, mm, off));
        if (lane == 0) SV[0] = mm;
    }
    __syncthreads();

    float e = 0.f;
    if (tid < TPAD) {
        e = expf(SC[tid] - SV[0]);
        WG[tid] = e;
    }
    #pragma unroll
    for (int off = 16; off > 0; off >>= 1)
        e += __shfl_xor_sync(0xffffffffu, e, off);
    if (lane == 0) RED[warp] = e;
    __syncthreads();
    if (warp == 0) {
        float t2 = (lane < 7) ? RED[lane] : 0.f;
        #pragma unroll
        for (int off = 4; off > 0; off >>= 1)
            t2 += __shfl_xor_sync(0xffffffffu, t2, off);
        if (lane == 0) SV[1] = t2;
    }
    __syncthreads();

    {
        float a0 = 0.f, a1 = 0.f;
        #pragma unroll 5
        for (int i = 0; i < 25; ++i) {
            int t = warp + 8 * i;           // 8*25 = 200 exactly
            float wv = WG[t];
            int row = hist[b * T_LEN + t];
            float2 v = *(const float2*)(item_table + (long)row * E_DIM + 2 * lane);
            a0 += wv * v.x;
            a1 += wv * v.y;
        }
        *(float2*)(ACC + warp * 64 + 2 * lane) = make_float2(a0, a1);
    }
    __syncthreads();
    if (tid < 64) {
        float v = ACC[tid] + ACC[64 + tid] + ACC[128 + tid] + ACC[192 + tid]
                + ACC[256 + tid] + ACC[320 + tid] + ACC[384 + tid] + ACC[448 + tid];
        g_interest[(long)b * E_DIM + tid] = v / SV[1];
    }
}

// ---------------------------------------------------------------------------
// Kernel C: final MLP via bf16 MMA, B-fragment prefetch pipeline.
// 16 rows/CTA, 256 thr (8 warps), grid 256, 2 CTAs/SM (128 regs).
// ---------------------------------------------------------------------------
#define MC_AH   0
#define MC_AL   2240
#define MC_H2H  4480
#define MC_H2L  (4480 + 2112)
#define MC_B1   (4480 + 4224)
#define MC_B2   (MC_B1 + 256)
#define MC_WO   (MC_B2 + 128)
#define MC_R    (MC_WO + 128)
#define SMEMC_WORDS (MC_R + 128)
#define SMEMC_BYTES (SMEMC_WORDS * 4)

__global__ void __launch_bounds__(256, 2)
din_mlp_kernel(const int* __restrict__ tgt,
               const int* __restrict__ sf,
               const float* __restrict__ dense,
               const float* __restrict__ item_table,
               const float* __restrict__ user_table,
               const float* __restrict__ ctx_table,
               const float* __restrict__ b1, const float* __restrict__ b2,
               const float* __restrict__ ow, const float* __restrict__ ob,
               float* __restrict__ out)
{
    extern __shared__ uint32_t smw[];
    uint32_t* AH  = smw + MC_AH;
    uint32_t* AL  = smw + MC_AL;
    uint32_t* H2H = smw + MC_H2H;
    uint32_t* H2L = smw + MC_H2L;
    float* B1S = (float*)(smw + MC_B1);
    float* B2S = (float*)(smw + MC_B2);
    float* WOS = (float*)(smw + MC_WO);
    float* R   = (float*)(smw + MC_R);

    const int b0   = blockIdx.x * 16;
    const int tid  = threadIdx.x;
    const int lane = tid & 31;
    const int wid  = tid >> 5;      // 0..7
    const int gid  = lane >> 2;     // 0..7
    const int tig  = lane & 3;      // 0..3

    // ---- stage features as packed bf16 hi/lo pairs ----
    for (int i = tid; i < 16 * 136; i += 256) {
        int bb = i / 136, w = i % 136;
        int gb = b0 + bb;
        int k = 2 * w;
        float e, o;
        if (k < 64) {
            const float* p = user_table + (long)sf[gb * 2] * 64 + k;
            e = p[0]; o = p[1];
        } else if (k < 128) {
            const float* p = ctx_table + (long)sf[gb * 2 + 1] * 64 + (k - 64);
            e = p[0]; o = p[1];
        } else if (k < 192) {
            const float* p = item_table + (long)tgt[gb] * 64 + (k - 128);
            e = p[0]; o = p[1];
        } else if (k < 256) {
            const float* p = g_interest + (long)gb * 64 + (k - 192);
            e = p[0]; o = p[1];
        } else {
            const float* p = dense + gb * 16 + (k - 256);
            e = p[0]; o = p[1];
        }
        uint32_t h, l;
        bsplit2(e, o, h, l);
        AH[bb * 140 + w] = h;
        AL[bb * 140 + w] = l;
    }
    if (tid < 256) B1S[tid] = b1[tid];
    if (tid < 128) { B2S[tid] = b2[tid]; WOS[tid] = ow[tid]; }
    __syncthreads();

    // ---- GEMM1: M16 x N256 x K272; warp owns n in [32*wid, 32*wid+32) ----
    const int n0 = wid * 32;
    {
        float acc[4][4];
        #pragma unroll
        for (int nt = 0; nt < 4; ++nt)
            #pragma unroll
            for (int p = 0; p < 4; ++p) acc[nt][p] = 0.f;

        // prologue: prefetch kc=0 B fragments
        uint32_t bh[4][2], bl[4][2];
        #pragma unroll
        for (int nt = 0; nt < 4; ++nt) {
            long boff = (long)(n0 + nt * 8 + gid) * 136 + tig;
            bh[nt][0] = g_m1H[boff]; bh[nt][1] = g_m1H[boff + 4];
            bl[nt][0] = g_m1L[boff]; bl[nt][1] = g_m1L[boff + 4];
        }

        for (int kc = 0; kc < 17; ++kc) {
            int a0 = gid * 140 + kc * 8 + tig;
            int a1 = (gid + 8) * 140 + kc * 8 + tig;
            uint32_t ah[4] = {AH[a0], AH[a1], AH[a0 + 4], AH[a1 + 4]};
            uint32_t al[4] = {AL[a0], AL[a1], AL[a0 + 4], AL[a1 + 4]};

            // prefetch next kc's B fragments while current MMAs issue
            uint32_t nbh[4][2], nbl[4][2];
            if (kc < 16) {
                #pragma unroll
                for (int nt = 0; nt < 4; ++nt) {
                    long boff = (long)(n0 + nt * 8 + gid) * 136 + (kc + 1) * 8 + tig;
                    nbh[nt][0] = g_m1H[boff]; nbh[nt][1] = g_m1H[boff + 4];
                    nbl[nt][0] = g_m1L[boff]; nbl[nt][1] = g_m1L[boff + 4];
                }
            }
            #pragma unroll
            for (int nt = 0; nt < 4; ++nt) {
                mmabf(acc[nt], ah, bh[nt]);
                mmabf(acc[nt], ah, bl[nt]);
                mmabf(acc[nt], al, bh[nt]);
            }
            if (kc < 16) {
                #pragma unroll
                for (int nt = 0; nt < 4; ++nt) {
                    bh[nt][0] = nbh[nt][0]; bh[nt][1] = nbh[nt][1];
                    bl[nt][0] = nbl[nt][0]; bl[nt][1] = nbl[nt][1];
                }
            }
        }
        // relu + b1, pack into H2 (k-pair layout for GEMM2's A, stride 132)
        #pragma unroll
        for (int nt = 0; nt < 4; ++nt) {
            int n = n0 + nt * 8 + 2 * tig;
            float q0 = B1S[n], q1 = B1S[n + 1];
            float v0 = fmaxf(acc[nt][0] + q0, 0.f);
            float v1 = fmaxf(acc[nt][1] + q1, 0.f);
            float v2 = fmaxf(acc[nt][2] + q0, 0.f);
            float v3 = fmaxf(acc[nt][3] + q1, 0.f);
            uint32_t h01, l01, h23, l23;
            bsplit2(v0, v1, h01, l01);
            bsplit2(v2, v3, h23, l23);
            int pw = (n0 >> 1) + nt * 4 + tig;      // pair index 0..127
            H2H[gid * 132 + pw]       = h01;
            H2L[gid * 132 + pw]       = l01;
            H2H[(gid + 8) * 132 + pw] = h23;
            H2L[(gid + 8) * 132 + pw] = l23;
        }
    }
    __syncthreads();

    // ---- GEMM2: M16 x N128 x K256; warp owns n in [16*wid, 16*wid+16) ----
    {
        const int n0b = wid * 16;
        float acc[2][4];
        #pragma unroll
        for (int nt = 0; nt < 2; ++nt)
            #pragma unroll
            for (int p = 0; p < 4; ++p) acc[nt][p] = 0.f;

        uint32_t bh[2][2], bl[2][2];
        #pragma unroll
        for (int nt = 0; nt < 2; ++nt) {
            long boff = (long)(n0b + nt * 8 + gid) * 128 + tig;
            bh[nt][0] = g_m2H[boff]; bh[nt][1] = g_m2H[boff + 4];
            bl[nt][0] = g_m2L[boff]; bl[nt][1] = g_m2L[boff + 4];
        }

        for (int kc = 0; kc < 16; ++kc) {
            int a0 = gid * 132 + kc * 8 + tig;
            int a1 = (gid + 8) * 132 + kc * 8 + tig;
            uint32_t ah[4] = {H2H[a0], H2H[a1], H2H[a0 + 4], H2H[a1 + 4]};
            uint32_t al[4] = {H2L[a0], H2L[a1], H2L[a0 + 4], H2L[a1 + 4]};

            uint32_t nbh[2][2], nbl[2][2];
            if (kc < 15) {
                #pragma unroll
                for (int nt = 0; nt < 2; ++nt) {
                    long boff = (long)(n0b + nt * 8 + gid) * 128 + (kc + 1) * 8 + tig;
                    nbh[nt][0] = g_m2H[boff]; nbh[nt][1] = g_m2H[boff + 4];
                    nbl[nt][0] = g_m2L[boff]; nbl[nt][1] = g_m2L[boff + 4];
                }
            }
            #pragma unroll
            for (int nt = 0; nt < 2; ++nt) {
                mmabf(acc[nt], ah, bh[nt]);
                mmabf(acc[nt], ah, bl[nt]);
                mmabf(acc[nt], al, bh[nt]);
            }
            if (kc < 15) {
                #pragma unroll
                for (int nt = 0; nt < 2; ++nt) {
                    bh[nt][0] = nbh[nt][0]; bh[nt][1] = nbh[nt][1];
                    bl[nt][0] = nbl[nt][0]; bl[nt][1] = nbl[nt][1];
                }
            }
        }
        float s0 = 0.f, s8 = 0.f;
        #pragma unroll
        for (int nt = 0; nt < 2; ++nt) {
            int n = n0b + nt * 8 + 2 * tig;
            float bb0 = B2S[n], bb1 = B2S[n + 1];
            float w0 = WOS[n],  w1v = WOS[n + 1];
            s0 += fmaxf(acc[nt][0] + bb0, 0.f) * w0 + fmaxf(acc[nt][1] + bb1, 0.f) * w1v;
            s8 += fmaxf(acc[nt][2] + bb0, 0.f) * w0 + fmaxf(acc[nt][3] + bb1, 0.f) * w1v;
        }
        s0 += __shfl_xor_sync(0xffffffffu, s0, 1);
        s0 += __shfl_xor_sync(0xffffffffu, s0, 2);
        s8 += __shfl_xor_sync(0xffffffffu, s8, 1);
        s8 += __shfl_xor_sync(0xffffffffu, s8, 2);
        if (tig == 0) {
            R[wid * 16 + gid]     = s0;
            R[wid * 16 + gid + 8] = s8;
        }
    }
    __syncthreads();
    if (tid < 16) {
        float s = ob[0];
        #pragma unroll
        for (int w = 0; w < 8; ++w) s += R[w * 16 + tid];
        out[b0 + tid] = s;
    }
}

// ---------------------------------------------------------------------------
extern "C" void kernel_launch(void* const* d_in, const int* in_sizes, int n_in,
                              void* d_out, int out_size)
{
    const int*   tgt   = (const int*)d_in[0];
    const int*   hist  = (const int*)d_in[1];
    const int*   mask  = (const int*)d_in[2];
    const int*   sf    = (const int*)d_in[3];
    const float* dense = (const float*)d_in[4];
    const float* item_table = (const float*)d_in[5];
    const float* user_table = (const float*)d_in[6];
    const float* ctx_table  = (const float*)d_in[7];
    const float* att_w1 = (const float*)d_in[8];
    const float* att_b1 = (const float*)d_in[9];
    const float* att_w2 = (const float*)d_in[10];
    const float* att_b2 = (const float*)d_in[11];
    const float* att_wo = (const float*)d_in[12];
    const float* att_bo = (const float*)d_in[13];
    const float* mlp_w1 = (const float*)d_in[14];
    const float* mlp_b1 = (const float*)d_in[15];
    const float* mlp_w2 = (const float*)d_in[16];
    const float* mlp_b2 = (const float*)d_in[17];
    const float* out_w  = (const float*)d_in[18];
    const float* out_b  = (const float*)d_in[19];
    float*       out    = (float*)d_out;

    cudaFuncSetAttribute(din_scores_kernel, cudaFuncAttributeMaxDynamicSharedMemorySize, SMEMA_BYTES);
    cudaFuncSetAttribute(din_mlp_kernel,    cudaFuncAttributeMaxDynamicSharedMemorySize, SMEMC_BYTES);

    din_prep_kernel<<<PACK_BLOCKS + B_ROWS, 256>>>(
        tgt, item_table, att_w1, att_b1, att_w2, mlp_w1, mlp_w2);

    din_scores_kernel<<<B_ROWS * 2, 256, SMEMA_BYTES>>>(
        tgt, hist, mask, att_b2, att_wo, att_bo);

    din_softmax_kernel<<<B_ROWS, 256>>>(hist, item_table);

    din_mlp_kernel<<<B_ROWS / 16, 256, SMEMC_BYTES>>>(
        tgt, sf, dense, item_table, user_table, ctx_table,
        mlp_b1, mlp_b2, out_w, out_b, out);
}